// round 1
// baseline (speedup 1.0000x reference)
#include <cuda_runtime.h>
#include <math.h>

// ---------------------------------------------------------------------------
// StarTransformerLayer: B=8, L=4096, H=256, NH=8, HD=32, 2 iterations.
// Key algebraic optimization: the 5 satellite keys per token are gathers of
// linear projections of {cur, x, center}; project each ONCE instead of 5x.
// ---------------------------------------------------------------------------

namespace {
constexpr int Bn  = 8;
constexpr int Ln  = 4096;
constexpr int Hn  = 256;
constexpr int NHn = 8;
constexpr int HDn = 32;
constexpr int Mn  = Bn * Ln;          // 32768 tokens
constexpr float SCALE = 0.17677669529663688f;   // 1/sqrt(32)
constexpr float LNEPS = 1e-12f;
}

// ---- scratch (device globals; allocation-free per harness rules) ----------
__device__ float g_cur [Mn * Hn];
__device__ float g_Q   [Mn * Hn];
__device__ float g_Kc  [Mn * Hn];
__device__ float g_Vc  [Mn * Hn];
__device__ float g_Kx  [Mn * Hn];
__device__ float g_Vx  [Mn * Hn];
__device__ float g_ctx [Mn * Hn];
__device__ float g_tmp [Mn * Hn];
__device__ float g_Krel[Mn * Hn];
__device__ float g_Vrel[Mn * Hn];

__device__ float g_center[Bn * Hn];
__device__ float g_Kcen [Bn * Hn];
__device__ float g_Vcen [Bn * Hn];
__device__ float g_Qrel [Bn * Hn];
__device__ float g_Krel0[Bn * Hn];
__device__ float g_Vrel0[Bn * Hn];
__device__ float g_relctx[Bn * Hn];

// ---------------------------------------------------------------------------
// elementwise copy (float4)
// ---------------------------------------------------------------------------
__global__ void copyf4_kernel(const float4* __restrict__ src,
                              float4* __restrict__ dst, int n4) {
    int i = blockIdx.x * blockDim.x + threadIdx.x;
    if (i < n4) dst[i] = src[i];
}

__global__ void copy_center_out_kernel(float* __restrict__ dst) {
    int i = blockIdx.x * blockDim.x + threadIdx.x;
    dst[i] = g_center[i];
}

// center = mean over L of x  (one block per batch; thread h strides L)
__global__ void mean_kernel(const float* __restrict__ x) {
    int b = blockIdx.x;
    int h = threadIdx.x;
    const float* p = x + (size_t)b * Ln * Hn + h;
    float s = 0.f;
    for (int l = 0; l < Ln; l++) s += p[(size_t)l * Hn];
    g_center[b * Hn + h] = s * (1.f / Ln);
}

// ---------------------------------------------------------------------------
// SGEMM: C[M,256] = A[M,256] @ W[256,256] + bias.  BM=BN=128, BK=8,
// 256 threads, 8x8 microtile (1 B/FMA -> at the LDS crossbar limit).
// ---------------------------------------------------------------------------
__global__ __launch_bounds__(256, 2)
void sgemm_bias_kernel(const float* __restrict__ A, const float* __restrict__ W,
                       const float* __restrict__ bias, float* __restrict__ C) {
    __shared__ float As[8][128];
    __shared__ float Bs[8][128];
    const int K = 256, N = 256;
    const int bm = blockIdx.y * 128;
    const int bn = blockIdx.x * 128;
    const int tid = threadIdx.x;

    const int arow = tid >> 1;            // 0..127
    const int acol = (tid & 1) * 4;       // 0 or 4
    const int brow = tid >> 5;            // 0..7
    const int bcol = (tid & 31) * 4;      // 0..124
    const int ty = tid >> 4;              // 0..15  -> rows ty*8..
    const int tx = tid & 15;              // 0..15  -> cols tx*8..

    float acc[8][8];
#pragma unroll
    for (int i = 0; i < 8; i++)
#pragma unroll
        for (int j = 0; j < 8; j++) acc[i][j] = 0.f;

    const float* Aptr = A + (size_t)(bm + arow) * K + acol;
    const float* Wptr = W + (size_t)brow * N + bn + bcol;

    for (int k0 = 0; k0 < K; k0 += 8) {
        float4 av = *(const float4*)(Aptr + k0);
        float4 bv = *(const float4*)(Wptr + (size_t)k0 * N);
        As[acol + 0][arow] = av.x;
        As[acol + 1][arow] = av.y;
        As[acol + 2][arow] = av.z;
        As[acol + 3][arow] = av.w;
        *(float4*)(&Bs[brow][bcol]) = bv;
        __syncthreads();
#pragma unroll
        for (int kk = 0; kk < 8; kk++) {
            float a[8], b[8];
            *(float4*)(a)     = *(const float4*)(&As[kk][ty * 8]);
            *(float4*)(a + 4) = *(const float4*)(&As[kk][ty * 8 + 4]);
            *(float4*)(b)     = *(const float4*)(&Bs[kk][tx * 8]);
            *(float4*)(b + 4) = *(const float4*)(&Bs[kk][tx * 8 + 4]);
#pragma unroll
            for (int i = 0; i < 8; i++)
#pragma unroll
                for (int j = 0; j < 8; j++)
                    acc[i][j] += a[i] * b[j];
        }
        __syncthreads();
    }

#pragma unroll
    for (int i = 0; i < 8; i++) {
        float* crow = C + (size_t)(bm + ty * 8 + i) * N + bn + tx * 8;
#pragma unroll
        for (int j = 0; j < 8; j += 4) {
            float4 o;
            o.x = acc[i][j + 0] + bias[bn + tx * 8 + j + 0];
            o.y = acc[i][j + 1] + bias[bn + tx * 8 + j + 1];
            o.z = acc[i][j + 2] + bias[bn + tx * 8 + j + 2];
            o.w = acc[i][j + 3] + bias[bn + tx * 8 + j + 3];
            *(float4*)(crow + j) = o;
        }
    }
}

// ---------------------------------------------------------------------------
// center projections: Kcen,Vcen (sat) + Qrel,Krel0,Vrel0 (rel), from current
// center. grid = 5*B blocks, 256 threads (thread n = output column).
// ---------------------------------------------------------------------------
__global__ void proj_center_kernel(
    const float* __restrict__ satWk, const float* __restrict__ satbk,
    const float* __restrict__ satWv, const float* __restrict__ satbv,
    const float* __restrict__ relWq, const float* __restrict__ relbq,
    const float* __restrict__ relWk, const float* __restrict__ relbk,
    const float* __restrict__ relWv, const float* __restrict__ relbv) {
    __shared__ float c[Hn];
    int b   = blockIdx.x % Bn;
    int sel = blockIdx.x / Bn;
    int n   = threadIdx.x;
    c[n] = g_center[b * Hn + n];
    __syncthreads();
    const float* W; const float* bi; float* out;
    switch (sel) {
        case 0: W = satWk; bi = satbk; out = g_Kcen;  break;
        case 1: W = satWv; bi = satbv; out = g_Vcen;  break;
        case 2: W = relWq; bi = relbq; out = g_Qrel;  break;
        case 3: W = relWk; bi = relbk; out = g_Krel0; break;
        default: W = relWv; bi = relbv; out = g_Vrel0; break;
    }
    float s = 0.f;
#pragma unroll 8
    for (int k = 0; k < Hn; k++) s += c[k] * W[k * Hn + n];
    out[b * Hn + n] = s + bi[n];
}

// ---------------------------------------------------------------------------
// satellite attention: 5 keys per token, warp per head, lane per head-dim.
// keys = {cur[(l+1)%L], cur[l], cur[l==0?L-1:0], x[l], center}
// ---------------------------------------------------------------------------
__global__ __launch_bounds__(256)
void sat_attn_kernel() {
    int token = blockIdx.x;               // 0..Mn-1
    int b = token >> 12;
    int l = token & (Ln - 1);
    int h = threadIdx.x >> 5;
    int d = threadIdx.x & 31;
    int col = h * HDn + d;

    size_t ic   = (size_t)token * Hn + col;
    int lb = (l + 1) & (Ln - 1);
    int la = (l == 0) ? (Ln - 1) : 0;
    size_t ibe  = ((size_t)(b * Ln + lb)) * Hn + col;
    size_t iaf  = ((size_t)(b * Ln + la)) * Hn + col;
    size_t icen = (size_t)b * Hn + col;

    float q  = g_Q[ic];
    float s0 = q * g_Kc[ibe];
    float s1 = q * g_Kc[ic];
    float s2 = q * g_Kc[iaf];
    float s3 = q * g_Kx[ic];
    float s4 = q * g_Kcen[icen];
#pragma unroll
    for (int off = 16; off; off >>= 1) {
        s0 += __shfl_xor_sync(0xffffffffu, s0, off);
        s1 += __shfl_xor_sync(0xffffffffu, s1, off);
        s2 += __shfl_xor_sync(0xffffffffu, s2, off);
        s3 += __shfl_xor_sync(0xffffffffu, s3, off);
        s4 += __shfl_xor_sync(0xffffffffu, s4, off);
    }
    s0 *= SCALE; s1 *= SCALE; s2 *= SCALE; s3 *= SCALE; s4 *= SCALE;
    float mx = fmaxf(fmaxf(fmaxf(s0, s1), fmaxf(s2, s3)), s4);
    float e0 = expf(s0 - mx), e1 = expf(s1 - mx), e2 = expf(s2 - mx);
    float e3 = expf(s3 - mx), e4 = expf(s4 - mx);
    float inv = 1.f / (e0 + e1 + e2 + e3 + e4);
    float ctx = (e0 * g_Vc[ibe] + e1 * g_Vc[ic] + e2 * g_Vc[iaf] +
                 e3 * g_Vx[ic] + e4 * g_Vcen[icen]) * inv;
    g_ctx[ic] = ctx;
}

// ---------------------------------------------------------------------------
// row LayerNorm(relu(tmp + cur)) -> cur, one block per row.
// ---------------------------------------------------------------------------
__global__ __launch_bounds__(256)
void ln_rows_kernel(const float* __restrict__ tmp, float* __restrict__ cur,
                    const float* __restrict__ w, const float* __restrict__ bvec) {
    __shared__ float red[8];
    int row = blockIdx.x;
    int h = threadIdx.x;
    size_t idx = (size_t)row * Hn + h;
    float v = fmaxf(tmp[idx] + cur[idx], 0.f);

    float s = v;
#pragma unroll
    for (int off = 16; off; off >>= 1) s += __shfl_xor_sync(0xffffffffu, s, off);
    if ((h & 31) == 0) red[h >> 5] = s;
    __syncthreads();
    float tot = 0.f;
#pragma unroll
    for (int i = 0; i < 8; i++) tot += red[i];
    float mean = tot * (1.f / Hn);
    __syncthreads();

    float dv = v - mean;
    float s2 = dv * dv;
#pragma unroll
    for (int off = 16; off; off >>= 1) s2 += __shfl_xor_sync(0xffffffffu, s2, off);
    if ((h & 31) == 0) red[h >> 5] = s2;
    __syncthreads();
    tot = 0.f;
#pragma unroll
    for (int i = 0; i < 8; i++) tot += red[i];
    float var = tot * (1.f / Hn);

    cur[idx] = w[h] * dv * rsqrtf(var + LNEPS) + bvec[h];
}

// ---------------------------------------------------------------------------
// relay attention: per (b,h), online softmax over 4097 keys
// key j=0 -> center projection, j>=1 -> cur projection row j-1.
// ---------------------------------------------------------------------------
__global__ __launch_bounds__(256)
void rel_attn_kernel() {
    __shared__ float qs[HDn];
    __shared__ float sm[256], ss[256];
    __shared__ float sacc[256 * HDn];     // 32 KB

    int b = blockIdx.x >> 3;
    int h = blockIdx.x & 7;
    int t = threadIdx.x;

    if (t < HDn) qs[t] = g_Qrel[b * Hn + h * HDn + t];
    __syncthreads();

    float m = -1e30f, ssum = 0.f;
    float acc[HDn];
#pragma unroll
    for (int d = 0; d < HDn; d++) acc[d] = 0.f;

    for (int j = t; j <= Ln; j += 256) {
        const float* kv; const float* vv;
        if (j == 0) {
            kv = g_Krel0 + b * Hn + h * HDn;
            vv = g_Vrel0 + b * Hn + h * HDn;
        } else {
            size_t base = ((size_t)(b * Ln + j - 1)) * Hn + h * HDn;
            kv = g_Krel + base;
            vv = g_Vrel + base;
        }
        float s = 0.f;
#pragma unroll
        for (int d = 0; d < HDn; d += 4) {
            float4 k4 = *(const float4*)(kv + d);
            s += qs[d] * k4.x + qs[d + 1] * k4.y + qs[d + 2] * k4.z + qs[d + 3] * k4.w;
        }
        s *= SCALE;
        float mn = fmaxf(m, s);
        float corr = expf(m - mn);
        float p = expf(s - mn);
        ssum = ssum * corr + p;
#pragma unroll
        for (int d = 0; d < HDn; d += 4) {
            float4 v4 = *(const float4*)(vv + d);
            acc[d + 0] = acc[d + 0] * corr + p * v4.x;
            acc[d + 1] = acc[d + 1] * corr + p * v4.y;
            acc[d + 2] = acc[d + 2] * corr + p * v4.z;
            acc[d + 3] = acc[d + 3] * corr + p * v4.w;
        }
        m = mn;
    }

    sm[t] = m; ss[t] = ssum;
#pragma unroll
    for (int d = 0; d < HDn; d++) sacc[t * HDn + d] = acc[d];
    __syncthreads();

    for (int stride = 128; stride > 0; stride >>= 1) {
        if (t < stride) {
            float m1 = sm[t], m2 = sm[t + stride];
            float mn = fmaxf(m1, m2);
            float c1 = expf(m1 - mn), c2 = expf(m2 - mn);
            sm[t] = mn;
            ss[t] = ss[t] * c1 + ss[t + stride] * c2;
            for (int d = 0; d < HDn; d++)
                sacc[t * HDn + d] = sacc[t * HDn + d] * c1 + sacc[(t + stride) * HDn + d] * c2;
        }
        __syncthreads();
    }

    if (t < HDn)
        g_relctx[b * Hn + h * HDn + t] = sacc[t] / ss[0];
}

// ---------------------------------------------------------------------------
// relay epilogue: center = LN(relu(relctx @ Wo + bo + center)); one block/b.
// ---------------------------------------------------------------------------
__global__ __launch_bounds__(256)
void rel_epi_kernel(const float* __restrict__ Wo, const float* __restrict__ bo,
                    const float* __restrict__ lnw, const float* __restrict__ lnb) {
    __shared__ float cx[Hn];
    __shared__ float red[8];
    int b = blockIdx.x;
    int n = threadIdx.x;
    cx[n] = g_relctx[b * Hn + n];
    float resid = g_center[b * Hn + n];
    __syncthreads();
    float s = 0.f;
#pragma unroll 8
    for (int k = 0; k < Hn; k++) s += cx[k] * Wo[k * Hn + n];
    float v = fmaxf(s + bo[n] + resid, 0.f);

    float r = v;
#pragma unroll
    for (int off = 16; off; off >>= 1) r += __shfl_xor_sync(0xffffffffu, r, off);
    if ((n & 31) == 0) red[n >> 5] = r;
    __syncthreads();
    float tot = 0.f;
#pragma unroll
    for (int i = 0; i < 8; i++) tot += red[i];
    float mean = tot * (1.f / Hn);
    __syncthreads();

    float dv = v - mean;
    float r2 = dv * dv;
#pragma unroll
    for (int off = 16; off; off >>= 1) r2 += __shfl_xor_sync(0xffffffffu, r2, off);
    if ((n & 31) == 0) red[n >> 5] = r2;
    __syncthreads();
    tot = 0.f;
#pragma unroll
    for (int i = 0; i < 8; i++) tot += red[i];
    float var = tot * (1.f / Hn);

    g_center[b * Hn + n] = lnw[n] * dv * rsqrtf(var + LNEPS) + lnb[n];
}

// ---------------------------------------------------------------------------
extern "C" void kernel_launch(void* const* d_in, const int* in_sizes, int n_in,
                              void* d_out, int out_size) {
    const float* x     = (const float*)d_in[0];
    const float* satWq = (const float*)d_in[1];  const float* satbq = (const float*)d_in[2];
    const float* satWk = (const float*)d_in[3];  const float* satbk = (const float*)d_in[4];
    const float* satWv = (const float*)d_in[5];  const float* satbv = (const float*)d_in[6];
    const float* satWo = (const float*)d_in[7];  const float* satbo = (const float*)d_in[8];
    const float* relWq = (const float*)d_in[9];  const float* relbq = (const float*)d_in[10];
    const float* relWk = (const float*)d_in[11]; const float* relbk = (const float*)d_in[12];
    const float* relWv = (const float*)d_in[13]; const float* relbv = (const float*)d_in[14];
    const float* relWo = (const float*)d_in[15]; const float* relbo = (const float*)d_in[16];
    const float* slnw  = (const float*)d_in[17]; const float* slnb  = (const float*)d_in[18];
    const float* rlnw  = (const float*)d_in[19]; const float* rlnb  = (const float*)d_in[20];
    float* out = (float*)d_out;

    float *cur, *Q, *Kc, *Vc, *Kx, *Vx, *ctx, *tmp, *Krel, *Vrel;
    cudaGetSymbolAddress((void**)&cur,  g_cur);
    cudaGetSymbolAddress((void**)&Q,    g_Q);
    cudaGetSymbolAddress((void**)&Kc,   g_Kc);
    cudaGetSymbolAddress((void**)&Vc,   g_Vc);
    cudaGetSymbolAddress((void**)&Kx,   g_Kx);
    cudaGetSymbolAddress((void**)&Vx,   g_Vx);
    cudaGetSymbolAddress((void**)&ctx,  g_ctx);
    cudaGetSymbolAddress((void**)&tmp,  g_tmp);
    cudaGetSymbolAddress((void**)&Krel, g_Krel);
    cudaGetSymbolAddress((void**)&Vrel, g_Vrel);

    const int n4 = Mn * Hn / 4;
    dim3 gg(Hn / 128, Mn / 128);   // (2, 256)

    // init: cur = x; center = mean_L(x); Kx/Vx loop-invariant projections
    copyf4_kernel<<<(n4 + 255) / 256, 256>>>((const float4*)x, (float4*)cur, n4);
    mean_kernel<<<Bn, Hn>>>(x);
    sgemm_bias_kernel<<<gg, 256>>>(x, satWk, satbk, Kx);
    sgemm_bias_kernel<<<gg, 256>>>(x, satWv, satbv, Vx);

    for (int it = 0; it < 2; it++) {
        proj_center_kernel<<<5 * Bn, Hn>>>(satWk, satbk, satWv, satbv,
                                           relWq, relbq, relWk, relbk, relWv, relbv);
        sgemm_bias_kernel<<<gg, 256>>>(cur, satWq, satbq, Q);
        sgemm_bias_kernel<<<gg, 256>>>(cur, satWk, satbk, Kc);
        sgemm_bias_kernel<<<gg, 256>>>(cur, satWv, satbv, Vc);
        sat_attn_kernel<<<Mn, 256>>>();
        sgemm_bias_kernel<<<gg, 256>>>(ctx, satWo, satbo, tmp);
        ln_rows_kernel<<<Mn, Hn>>>(tmp, cur, slnw, slnb);
        sgemm_bias_kernel<<<gg, 256>>>(cur, relWk, relbk, Krel);
        sgemm_bias_kernel<<<gg, 256>>>(cur, relWv, relbv, Vrel);
        rel_attn_kernel<<<Bn * NHn, 256>>>();
        rel_epi_kernel<<<Bn, Hn>>>(relWo, relbo, rlnw, rlnb);
    }

    copyf4_kernel<<<(n4 + 255) / 256, 256>>>((const float4*)cur, (float4*)out, n4);
    copy_center_out_kernel<<<Bn, Hn>>>(out + (size_t)Mn * Hn);
}

// round 3
// speedup vs baseline: 1.8070x; 1.8070x over previous
#include <cuda_runtime.h>
#include <cuda_fp16.h>
#include <math.h>
#include <stdint.h>

// ---------------------------------------------------------------------------
// StarTransformerLayer, GB300 (compute_103 PTX -> mma.sync path, no tcgen05).
// B=8, L=4096, H=256, NH=8, HD=32, 2 iterations.
// GEMMs: fp16 split "triple" trick: A'=(ah,al,ah), B'=(bh,bh,bl) over K'=384,
// single mma.sync pass computes ah*bh + al*bh + ah*bl (fp32 accum).
// W pre-scaled by 256 (avoids fp16 subnormal bl), epilogue multiplies 1/256.
// ---------------------------------------------------------------------------

namespace {
constexpr int Bn  = 8;
constexpr int Ln  = 4096;
constexpr int Hn  = 256;
constexpr int NHn = 8;
constexpr int HDn = 32;
constexpr int Mn  = Bn * Ln;          // 32768
constexpr int Kp  = 384;              // 3 * 128? no: 3 * Hn/2... = 3*Hn/2? K'=3*256/2
// K' = 3 * Hn / 2 is wrong; K' = 3 * Hn / 2 -> 384 happens to equal 3*256/2, but
// derivation is: per original k we emit 3 fp16 -> K' = 3*Hn/2? No: 3*256 = 768?
// CORRECT: per original k we emit 3 entries -> K' = 3*Hn = 768?? No — see below:
// we emit the triple per original k, so K' = 3*Hn/2 is wrong and 3*Hn=768 is wrong
// too unless... A row has Hn=256 original k's, each -> 3 fp16 => 768.
constexpr float SCALE = 0.17677669529663688f;   // 1/sqrt(32)
constexpr float LNEPS = 1e-12f;
constexpr float INVW  = 1.f / 256.f;            // undo weight pre-scale
}
// NOTE: K' really is 3*Hn = 768. All triple-layout code below uses KT=768.
namespace { constexpr int KT = 3 * Hn; }        // 768 fp16 per A' row

// ---- scratch (device globals) ---------------------------------------------
__device__ float  g_cur [Mn * Hn];
__device__ __align__(16) __half g_curT[(size_t)Mn * KT];
__device__ __align__(16) __half g_ctxT[(size_t)Mn * KT];
__device__ __align__(16) __half g_BT  [6 * (size_t)KT * Hn];
__device__ float  g_Q   [Mn * Hn];
__device__ float  g_Kc  [Mn * Hn];
__device__ float  g_Vc  [Mn * Hn];
__device__ float  g_Kx  [Mn * Hn];
__device__ float  g_Vx  [Mn * Hn];
__device__ float  g_tmp [Mn * Hn];
__device__ float  g_Krel[Mn * Hn];
__device__ float  g_Vrel[Mn * Hn];

__device__ float g_center[Bn * Hn];
__device__ float g_Kcen [Bn * Hn];
__device__ float g_Vcen [Bn * Hn];
__device__ float g_Qrel [Bn * Hn];
__device__ float g_Krel0[Bn * Hn];
__device__ float g_Vrel0[Bn * Hn];
__device__ float g_relctx[Bn * Hn];
__device__ float g_cpart[Bn * 16 * Hn];

__device__ float g_pm[512];
__device__ float g_ps[512];
__device__ float g_pacc[512 * HDn];

// ---------------------------------------------------------------------------
// helpers
// ---------------------------------------------------------------------------
__device__ __forceinline__ uint32_t smem_u32(const void* p) {
    uint32_t a;
    asm("{ .reg .u64 t; cvta.to.shared.u64 t, %1; cvt.u32.u64 %0, t; }"
        : "=r"(a) : "l"(p));
    return a;
}
__device__ __forceinline__ void cp16(uint32_t s, const void* g) {
    asm volatile("cp.async.cg.shared.global [%0], [%1], 16;" :: "r"(s), "l"(g));
}
__device__ __forceinline__ void cp_commit() {
    asm volatile("cp.async.commit_group;" ::: "memory");
}
__device__ __forceinline__ void ldm_x4(uint32_t* r, uint32_t a) {
    asm volatile("ldmatrix.sync.aligned.m8n8.x4.shared.b16 {%0,%1,%2,%3}, [%4];"
                 : "=r"(r[0]), "=r"(r[1]), "=r"(r[2]), "=r"(r[3]) : "r"(a));
}
__device__ __forceinline__ void ldm_x4t(uint32_t* r, uint32_t a) {
    asm volatile("ldmatrix.sync.aligned.m8n8.x4.trans.shared.b16 {%0,%1,%2,%3}, [%4];"
                 : "=r"(r[0]), "=r"(r[1]), "=r"(r[2]), "=r"(r[3]) : "r"(a));
}
__device__ __forceinline__ void mma16816(float* c, const uint32_t* a,
                                         const uint32_t* b) {
    asm volatile(
        "mma.sync.aligned.m16n8k16.row.col.f32.f16.f16.f32 "
        "{%0,%1,%2,%3}, {%4,%5,%6,%7}, {%8,%9}, {%0,%1,%2,%3};"
        : "+f"(c[0]), "+f"(c[1]), "+f"(c[2]), "+f"(c[3])
        : "r"(a[0]), "r"(a[1]), "r"(a[2]), "r"(a[3]), "r"(b[0]), "r"(b[1]));
}

// ---------------------------------------------------------------------------
// GEMM: C[M,256] = A'[M,768] @ B'[768,256] * (1/256) + bias
// CTA tile 128x128, 8 warps (2M x 4N), warp tile 64x32. KC=48, 3-stage cp.async.
// ---------------------------------------------------------------------------
namespace {
constexpr int LDA = 56;                 // 48 + 8 pad (fp16)
constexpr int LDB = 136;                // 128 + 8 pad
constexpr int ASTG = 128 * LDA;         // halfs
constexpr int BSTG = 48 * LDB;
constexpr int STG  = ASTG + BSTG;       // halfs per stage
constexpr int NCHUNK = KT / 48;         // 16
constexpr int GEMM_SMEM = STG * 2 * 3;  // 82176 bytes
}

__global__ __launch_bounds__(256, 2)
void hgemm_triple(const __half* __restrict__ Ap, const __half* __restrict__ Bp,
                  const float* __restrict__ bias, float* __restrict__ C) {
    extern __shared__ __align__(16) __half smh[];
    const int tid = threadIdx.x;
    const int bn = blockIdx.x * 128;
    const int bm = blockIdx.y * 128;
    const uint32_t sbase = smem_u32(smh);

    // per-thread cp.async slots: A 768 chunks16B (3/thr), B 768 (3/thr)
    uint32_t sA[3], sB[3];
    const __half* gAb[3];
    const __half* gBb[3];
#pragma unroll
    for (int i = 0; i < 3; i++) {
        int seg = tid + i * 256;
        int r = seg / 6, c = seg % 6;                 // A: 128 rows x 6
        sA[i] = (uint32_t)(r * LDA + c * 8) * 2;
        gAb[i] = Ap + (size_t)(bm + r) * KT + c * 8;
        int r2 = seg / 16, c2 = seg % 16;             // B: 48 rows x 16
        sB[i] = (uint32_t)(ASTG + r2 * LDB + c2 * 8) * 2;
        gBb[i] = Bp + (size_t)r2 * Hn + bn + c2 * 8;
    }

    auto load_chunk = [&](int j, int s) {
        uint32_t st = sbase + (uint32_t)(s * STG) * 2;
        const __half* ga = gAb[0] + j * 48;           // advance along K'
        const __half* gb = gBb[0] + (size_t)j * 48 * Hn;
#pragma unroll
        for (int i = 0; i < 3; i++)
            cp16(st + sA[i], gAb[i] + j * 48);
#pragma unroll
        for (int i = 0; i < 3; i++)
            cp16(st + sB[i], gBb[i] + (size_t)j * 48 * Hn);
        cp_commit();
        (void)ga; (void)gb;
    };

    const int warp = tid >> 5, lane = tid & 31;
    const int wm = (warp & 1) * 64;
    const int wn = (warp >> 1) * 32;
    const int lr = lane & 15;
    const int lc = (lane >> 4) * 8;

    float acc[4][4][4];
#pragma unroll
    for (int mi = 0; mi < 4; mi++)
#pragma unroll
        for (int ni = 0; ni < 4; ni++)
#pragma unroll
            for (int k = 0; k < 4; k++) acc[mi][ni][k] = 0.f;

    load_chunk(0, 0);
    load_chunk(1, 1);

    for (int j = 0; j < NCHUNK; j++) {
        const int s = j % 3;
        if (j >= NCHUNK - 2)
            asm volatile("cp.async.wait_group 0;" ::: "memory");
        else
            asm volatile("cp.async.wait_group 1;" ::: "memory");
        __syncthreads();
        if (j + 2 < NCHUNK) load_chunk(j + 2, (j + 2) % 3);

        const uint32_t st = sbase + (uint32_t)(s * STG) * 2;
#pragma unroll
        for (int ks = 0; ks < 48; ks += 16) {
            uint32_t a[4][4];
#pragma unroll
            for (int mi = 0; mi < 4; mi++)
                ldm_x4(a[mi], st + (uint32_t)((wm + mi * 16 + lr) * LDA + ks + lc) * 2);
            uint32_t b[2][4];
#pragma unroll
            for (int np = 0; np < 2; np++)
                ldm_x4t(b[np], st + (uint32_t)(ASTG + (ks + lr) * LDB
                                               + wn + np * 16 + lc) * 2);
#pragma unroll
            for (int mi = 0; mi < 4; mi++)
#pragma unroll
                for (int ni = 0; ni < 4; ni++)
                    mma16816(acc[mi][ni], a[mi], &b[ni >> 1][(ni & 1) * 2]);
        }
        __syncthreads();
    }

    // epilogue: *1/256 + bias
    const int g = lane >> 2, tg = (lane & 3) * 2;
#pragma unroll
    for (int mi = 0; mi < 4; mi++) {
#pragma unroll
        for (int ni = 0; ni < 4; ni++) {
            int row = bm + wm + mi * 16 + g;
            int col = bn + wn + ni * 8 + tg;
            float b0 = bias[col], b1 = bias[col + 1];
            float2 o0 = { acc[mi][ni][0] * INVW + b0, acc[mi][ni][1] * INVW + b1 };
            float2 o1 = { acc[mi][ni][2] * INVW + b0, acc[mi][ni][3] * INVW + b1 };
            *(float2*)(C + (size_t)row * Hn + col) = o0;
            *(float2*)(C + (size_t)(row + 8) * Hn + col) = o1;
        }
    }
}

// ---------------------------------------------------------------------------
// weight prep: B'[768,256] from W[256,256]: rows 3k=bh,3k+1=bh,3k+2=bl, W*256
// ---------------------------------------------------------------------------
__global__ void wprep_kernel(const float* __restrict__ W, __half* __restrict__ Bp) {
    int k = blockIdx.x, n = threadIdx.x;
    float w = W[(size_t)k * Hn + n] * 256.f;
    __half bh = __float2half_rn(w);
    __half bl = __float2half_rn(w - __half2float(bh));
    Bp[(size_t)(3 * k + 0) * Hn + n] = bh;
    Bp[(size_t)(3 * k + 1) * Hn + n] = bh;
    Bp[(size_t)(3 * k + 2) * Hn + n] = bl;
}

// ---------------------------------------------------------------------------
// x -> cur (fp32) + curT (fp16 triples). thread = 8 consecutive k of one row.
// ---------------------------------------------------------------------------
__global__ void splitcopy_kernel(const float* __restrict__ x) {
    int t = blockIdx.x * blockDim.x + threadIdx.x;   // Mn*Hn/8 threads
    int row = t >> 5;
    int k0 = (t & 31) * 8;
    const float* src = x + (size_t)row * Hn + k0;
    float* dst = g_cur + (size_t)row * Hn + k0;
    __half trip[24];
#pragma unroll
    for (int j = 0; j < 8; j++) {
        float a = src[j];
        dst[j] = a;
        __half ah = __float2half_rn(a);
        __half al = __float2half_rn(a - __half2float(ah));
        trip[3 * j + 0] = ah;
        trip[3 * j + 1] = al;
        trip[3 * j + 2] = ah;
    }
    uint4* o = (uint4*)(g_curT + (size_t)row * KT + 3 * k0);
    const uint4* ti = (const uint4*)trip;
    o[0] = ti[0]; o[1] = ti[1]; o[2] = ti[2];
}

__global__ void copyf4_kernel(const float4* __restrict__ src,
                              float4* __restrict__ dst, int n4) {
    int i = blockIdx.x * blockDim.x + threadIdx.x;
    if (i < n4) dst[i] = src[i];
}
__global__ void copy_center_out_kernel(float* __restrict__ dst) {
    int i = blockIdx.x * blockDim.x + threadIdx.x;
    dst[i] = g_center[i];
}

// center = mean over L of x, two stages
__global__ void meanpart_kernel(const float* __restrict__ x) {
    int c = blockIdx.x, b = blockIdx.y, h = threadIdx.x;
    const float* p = x + ((size_t)b * Ln + c * 256) * Hn + h;
    float s = 0.f;
    for (int l = 0; l < 256; l++) s += p[(size_t)l * Hn];
    g_cpart[(b * 16 + c) * Hn + h] = s;
}
__global__ void meancomb_kernel() {
    int b = blockIdx.x, h = threadIdx.x;
    float s = 0.f;
    for (int c = 0; c < 16; c++) s += g_cpart[(b * 16 + c) * Hn + h];
    g_center[b * Hn + h] = s * (1.f / Ln);
}

// ---------------------------------------------------------------------------
// center projections (tiny fp32)
// ---------------------------------------------------------------------------
__global__ void proj_center_kernel(
    const float* __restrict__ satWk, const float* __restrict__ satbk,
    const float* __restrict__ satWv, const float* __restrict__ satbv,
    const float* __restrict__ relWq, const float* __restrict__ relbq,
    const float* __restrict__ relWk, const float* __restrict__ relbk,
    const float* __restrict__ relWv, const float* __restrict__ relbv) {
    __shared__ float c[Hn];
    int b   = blockIdx.x % Bn;
    int sel = blockIdx.x / Bn;
    int n   = threadIdx.x;
    c[n] = g_center[b * Hn + n];
    __syncthreads();
    const float* W; const float* bi; float* out;
    switch (sel) {
        case 0: W = satWk; bi = satbk; out = g_Kcen;  break;
        case 1: W = satWv; bi = satbv; out = g_Vcen;  break;
        case 2: W = relWq; bi = relbq; out = g_Qrel;  break;
        case 3: W = relWk; bi = relbk; out = g_Krel0; break;
        default: W = relWv; bi = relbv; out = g_Vrel0; break;
    }
    float s = 0.f;
#pragma unroll 8
    for (int k = 0; k < Hn; k++) s += c[k] * W[k * Hn + n];
    out[b * Hn + n] = s + bi[n];
}

// ---------------------------------------------------------------------------
// satellite attention -> writes ctx triples
// ---------------------------------------------------------------------------
__global__ __launch_bounds__(256)
void sat_attn_kernel() {
    int token = blockIdx.x;
    int b = token >> 12;
    int l = token & (Ln - 1);
    int h = threadIdx.x >> 5;
    int d = threadIdx.x & 31;
    int col = h * HDn + d;

    size_t ic   = (size_t)token * Hn + col;
    int lb = (l + 1) & (Ln - 1);
    int la = (l == 0) ? (Ln - 1) : 0;
    size_t ibe  = ((size_t)(b * Ln + lb)) * Hn + col;
    size_t iaf  = ((size_t)(b * Ln + la)) * Hn + col;
    size_t icen = (size_t)b * Hn + col;

    float q  = g_Q[ic];
    float s0 = q * g_Kc[ibe];
    float s1 = q * g_Kc[ic];
    float s2 = q * g_Kc[iaf];
    float s3 = q * g_Kx[ic];
    float s4 = q * g_Kcen[icen];
#pragma unroll
    for (int off = 16; off; off >>= 1) {
        s0 += __shfl_xor_sync(0xffffffffu, s0, off);
        s1 += __shfl_xor_sync(0xffffffffu, s1, off);
        s2 += __shfl_xor_sync(0xffffffffu, s2, off);
        s3 += __shfl_xor_sync(0xffffffffu, s3, off);
        s4 += __shfl_xor_sync(0xffffffffu, s4, off);
    }
    s0 *= SCALE; s1 *= SCALE; s2 *= SCALE; s3 *= SCALE; s4 *= SCALE;
    float mx = fmaxf(fmaxf(fmaxf(s0, s1), fmaxf(s2, s3)), s4);
    float e0 = expf(s0 - mx), e1 = expf(s1 - mx), e2 = expf(s2 - mx);
    float e3 = expf(s3 - mx), e4 = expf(s4 - mx);
    float inv = 1.f / (e0 + e1 + e2 + e3 + e4);
    float ctx = (e0 * g_Vc[ibe] + e1 * g_Vc[ic] + e2 * g_Vc[iaf] +
                 e3 * g_Vx[ic] + e4 * g_Vcen[icen]) * inv;

    __half ah = __float2half_rn(ctx);
    __half al = __float2half_rn(ctx - __half2float(ah));
    size_t ot = (size_t)token * KT + 3 * col;
    g_ctxT[ot + 0] = ah;
    g_ctxT[ot + 1] = al;
    g_ctxT[ot + 2] = ah;
}

// ---------------------------------------------------------------------------
// LN(relu(tmp + cur)) -> cur + curT triples
// ---------------------------------------------------------------------------
__global__ __launch_bounds__(256)
void ln_rows_kernel(const float* __restrict__ tmp, float* __restrict__ cur,
                    const float* __restrict__ w, const float* __restrict__ bvec) {
    __shared__ float red[8];
    int row = blockIdx.x;
    int h = threadIdx.x;
    size_t idx = (size_t)row * Hn + h;
    float v = fmaxf(tmp[idx] + cur[idx], 0.f);

    float s = v;
#pragma unroll
    for (int off = 16; off; off >>= 1) s += __shfl_xor_sync(0xffffffffu, s, off);
    if ((h & 31) == 0) red[h >> 5] = s;
    __syncthreads();
    float tot = 0.f;
#pragma unroll
    for (int i = 0; i < 8; i++) tot += red[i];
    float mean = tot * (1.f / Hn);
    __syncthreads();

    float dv = v - mean;
    float s2 = dv * dv;
#pragma unroll
    for (int off = 16; off; off >>= 1) s2 += __shfl_xor_sync(0xffffffffu, s2, off);
    if ((h & 31) == 0) red[h >> 5] = s2;
    __syncthreads();
    tot = 0.f;
#pragma unroll
    for (int i = 0; i < 8; i++) tot += red[i];
    float var = tot * (1.f / Hn);

    float o = w[h] * dv * rsqrtf(var + LNEPS) + bvec[h];
    cur[idx] = o;
    __half ah = __float2half_rn(o);
    __half al = __float2half_rn(o - __half2float(ah));
    size_t ot = (size_t)row * KT + 3 * h;
    g_curT[ot + 0] = ah;
    g_curT[ot + 1] = al;
    g_curT[ot + 2] = ah;
}

// ---------------------------------------------------------------------------
// relay attention split-KV (512 blocks) + combine
// ---------------------------------------------------------------------------
__global__ __launch_bounds__(256)
void rel_part_kernel() {
    __shared__ float qs[HDn];
    __shared__ float sm[256], ss[256];
    __shared__ float sacc[256 * HDn];

    int bh = blockIdx.x >> 3;
    int sp = blockIdx.x & 7;
    int b = bh >> 3, h = bh & 7;
    int t = threadIdx.x;

    if (t < HDn) qs[t] = g_Qrel[b * Hn + h * HDn + t];
    __syncthreads();

    float m = -1e30f, ssum = 0.f;
    float acc[HDn];
#pragma unroll
    for (int d = 0; d < HDn; d++) acc[d] = 0.f;

    for (int j = sp * 256 + t; j <= Ln; j += 2048) {
        const float* kv; const float* vv;
        if (j == 0) {
            kv = g_Krel0 + b * Hn + h * HDn;
            vv = g_Vrel0 + b * Hn + h * HDn;
        } else {
            size_t base = ((size_t)(b * Ln + j - 1)) * Hn + h * HDn;
            kv = g_Krel + base;
            vv = g_Vrel + base;
        }
        float s = 0.f;
#pragma unroll
        for (int d = 0; d < HDn; d += 4) {
            float4 k4 = *(const float4*)(kv + d);
            s += qs[d] * k4.x + qs[d + 1] * k4.y + qs[d + 2] * k4.z + qs[d + 3] * k4.w;
        }
        s *= SCALE;
        float mn = fmaxf(m, s);
        float corr = expf(m - mn);
        float p = expf(s - mn);
        ssum = ssum * corr + p;
#pragma unroll
        for (int d = 0; d < HDn; d += 4) {
            float4 v4 = *(const float4*)(vv + d);
            acc[d + 0] = acc[d + 0] * corr + p * v4.x;
            acc[d + 1] = acc[d + 1] * corr + p * v4.y;
            acc[d + 2] = acc[d + 2] * corr + p * v4.z;
            acc[d + 3] = acc[d + 3] * corr + p * v4.w;
        }
        m = mn;
    }

    sm[t] = m; ss[t] = ssum;
#pragma unroll
    for (int d = 0; d < HDn; d++) sacc[t * HDn + d] = acc[d];
    __syncthreads();

    for (int stride = 128; stride > 0; stride >>= 1) {
        if (t < stride) {
            float m1 = sm[t], m2 = sm[t + stride];
            float mn = fmaxf(m1, m2);
            float c1 = expf(m1 - mn), c2 = expf(m2 - mn);
            sm[t] = mn;
            ss[t] = ss[t] * c1 + ss[t + stride] * c2;
            for (int d = 0; d < HDn; d++)
                sacc[t * HDn + d] = sacc[t * HDn + d] * c1 + sacc[(t + stride) * HDn + d] * c2;
        }
        __syncthreads();
    }

    if (t == 0) { g_pm[blockIdx.x] = sm[0]; g_ps[blockIdx.x] = ss[0]; }
    if (t < HDn) g_pacc[blockIdx.x * HDn + t] = sacc[t];
}

__global__ void rel_comb_kernel() {   // grid 64, 32 threads
    int bh = blockIdx.x;
    int d = threadIdx.x;
    float m = -1e30f;
#pragma unroll
    for (int sp = 0; sp < 8; sp++) m = fmaxf(m, g_pm[bh * 8 + sp]);
    float s = 0.f, a = 0.f;
#pragma unroll
    for (int sp = 0; sp < 8; sp++) {
        float c = expf(g_pm[bh * 8 + sp] - m);
        s += g_ps[bh * 8 + sp] * c;
        a += g_pacc[(bh * 8 + sp) * HDn + d] * c;
    }
    g_relctx[bh * HDn + d] = a / s;
}

// ---------------------------------------------------------------------------
// relay epilogue: center = LN(relu(relctx @ Wo + bo + center))
// ---------------------------------------------------------------------------
__global__ __launch_bounds__(256)
void rel_epi_kernel(const float* __restrict__ Wo, const float* __restrict__ bo,
                    const float* __restrict__ lnw, const float* __restrict__ lnb) {
    __shared__ float cx[Hn];
    __shared__ float red[8];
    int b = blockIdx.x;
    int n = threadIdx.x;
    cx[n] = g_relctx[b * Hn + n];
    float resid = g_center[b * Hn + n];
    __syncthreads();
    float s = 0.f;
#pragma unroll 8
    for (int k = 0; k < Hn; k++) s += cx[k] * Wo[k * Hn + n];
    float v = fmaxf(s + bo[n] + resid, 0.f);

    float r = v;
#pragma unroll
    for (int off = 16; off; off >>= 1) r += __shfl_xor_sync(0xffffffffu, r, off);
    if ((n & 31) == 0) red[n >> 5] = r;
    __syncthreads();
    float tot = 0.f;
#pragma unroll
    for (int i = 0; i < 8; i++) tot += red[i];
    float mean = tot * (1.f / Hn);
    __syncthreads();

    float dv = v - mean;
    float r2 = dv * dv;
#pragma unroll
    for (int off = 16; off; off >>= 1) r2 += __shfl_xor_sync(0xffffffffu, r2, off);
    if ((n & 31) == 0) red[n >> 5] = r2;
    __syncthreads();
    tot = 0.f;
#pragma unroll
    for (int i = 0; i < 8; i++) tot += red[i];
    float var = tot * (1.f / Hn);

    g_center[b * Hn + n] = lnw[n] * dv * rsqrtf(var + LNEPS) + lnb[n];
}

// ---------------------------------------------------------------------------
extern "C" void kernel_launch(void* const* d_in, const int* in_sizes, int n_in,
                              void* d_out, int out_size) {
    const float* x     = (const float*)d_in[0];
    const float* satWq = (const float*)d_in[1];  const float* satbq = (const float*)d_in[2];
    const float* satWk = (const float*)d_in[3];  const float* satbk = (const float*)d_in[4];
    const float* satWv = (const float*)d_in[5];  const float* satbv = (const float*)d_in[6];
    const float* satWo = (const float*)d_in[7];  const float* satbo = (const float*)d_in[8];
    const float* relWq = (const float*)d_in[9];  const float* relbq = (const float*)d_in[10];
    const float* relWk = (const float*)d_in[11]; const float* relbk = (const float*)d_in[12];
    const float* relWv = (const float*)d_in[13]; const float* relbv = (const float*)d_in[14];
    const float* relWo = (const float*)d_in[15]; const float* relbo = (const float*)d_in[16];
    const float* slnw  = (const float*)d_in[17]; const float* slnb  = (const float*)d_in[18];
    const float* rlnw  = (const float*)d_in[19]; const float* rlnb  = (const float*)d_in[20];
    float* out = (float*)d_out;

    float *cur, *Q, *Kc, *Vc, *Kx, *Vx, *tmp, *Krel, *Vrel;
    __half *curT, *ctxT, *BT;
    cudaGetSymbolAddress((void**)&cur,  g_cur);
    cudaGetSymbolAddress((void**)&Q,    g_Q);
    cudaGetSymbolAddress((void**)&Kc,   g_Kc);
    cudaGetSymbolAddress((void**)&Vc,   g_Vc);
    cudaGetSymbolAddress((void**)&Kx,   g_Kx);
    cudaGetSymbolAddress((void**)&Vx,   g_Vx);
    cudaGetSymbolAddress((void**)&tmp,  g_tmp);
    cudaGetSymbolAddress((void**)&Krel, g_Krel);
    cudaGetSymbolAddress((void**)&Vrel, g_Vrel);
    cudaGetSymbolAddress((void**)&curT, g_curT);
    cudaGetSymbolAddress((void**)&ctxT, g_ctxT);
    cudaGetSymbolAddress((void**)&BT,   g_BT);

    cudaFuncSetAttribute(hgemm_triple, cudaFuncAttributeMaxDynamicSharedMemorySize,
                         GEMM_SMEM);

    // weight prep: 0 satWq, 1 satWk, 2 satWv, 3 satWo, 4 relWk, 5 relWv
    const float* Wsrc[6] = {satWq, satWk, satWv, satWo, relWk, relWv};
    for (int wi = 0; wi < 6; wi++)
        wprep_kernel<<<Hn, Hn>>>(Wsrc[wi], BT + (size_t)wi * KT * Hn);

    splitcopy_kernel<<<Mn * Hn / 8 / 256, 256>>>(x);
    meanpart_kernel<<<dim3(16, Bn), Hn>>>(x);
    meancomb_kernel<<<Bn, Hn>>>();

    dim3 gg(Hn / 128, Mn / 128);   // (2, 256)
    #define GEMM(AT, WI, BIAS, CPTR) \
        hgemm_triple<<<gg, 256, GEMM_SMEM>>>(AT, BT + (size_t)(WI) * KT * Hn, BIAS, CPTR)

    GEMM(curT, 1, satbk, Kx);      // cur == x here
    GEMM(curT, 2, satbv, Vx);

    for (int it = 0; it < 2; it++) {
        proj_center_kernel<<<5 * Bn, Hn>>>(satWk, satbk, satWv, satbv,
                                           relWq, relbq, relWk, relbk, relWv, relbv);
        GEMM(curT, 0, satbq, Q);
        GEMM(curT, 1, satbk, Kc);
        GEMM(curT, 2, satbv, Vc);
        sat_attn_kernel<<<Mn, 256>>>();
        GEMM(ctxT, 3, satbo, tmp);
        ln_rows_kernel<<<Mn, Hn>>>(tmp, cur, slnw, slnb);
        GEMM(curT, 4, relbk, Krel);
        GEMM(curT, 5, relbv, Vrel);
        rel_part_kernel<<<Bn * NHn * 8, 256>>>();
        rel_comb_kernel<<<Bn * NHn, HDn>>>();
        rel_epi_kernel<<<Bn, Hn>>>(relWo, relbo, rlnw, rlnb);
    }
    #undef GEMM

    const int n4 = Mn * Hn / 4;
    copyf4_kernel<<<(n4 + 255) / 256, 256>>>((const float4*)cur, (float4*)out, n4);
    copy_center_out_kernel<<<Bn, Hn>>>(out + (size_t)Mn * Hn);
}

// round 6
// speedup vs baseline: 2.0769x; 1.1494x over previous
#include <cuda_runtime.h>
#include <cuda_fp16.h>
#include <math.h>
#include <stdint.h>

// ---------------------------------------------------------------------------
// StarTransformerLayer, GB300 (compute_103 PTX -> mma.sync path).
// B=8, L=4096, H=256, NH=8, HD=32, 2 iterations.
// GEMMs: fp16 split, BLOCK layout. A' = [ah | al] (512 halfs stored).
// B' = [bh | bh | bl] (768 rows). GEMM runs K'=768, mapping chunks 16..23 of A
// back onto the ah block, computing ah*bh + al*bh + ah*bl in one pass.
// W pre-scaled by 256 (keeps bl normal), epilogue multiplies by 1/256.
// ---------------------------------------------------------------------------

namespace {
constexpr int Bn  = 8;
constexpr int Ln  = 4096;
constexpr int Hn  = 256;
constexpr int NHn = 8;
constexpr int HDn = 32;
constexpr int Mn  = Bn * Ln;          // 32768
constexpr int KA  = 512;              // stored A' columns (ah | al)
constexpr int KTB = 768;              // B' rows (bh | bh | bl)
constexpr float SCALE = 0.17677669529663688f;   // 1/sqrt(32)
constexpr float LNEPS = 1e-12f;
constexpr float INVW  = 1.f / 256.f;
// GEMM tiling
constexpr int KC   = 32;
constexpr int NC   = KTB / KC;        // 24 chunks
constexpr int LDA  = 40;              // 32 + 8 pad (halfs)
constexpr int LDB  = 264;             // 256 + 8 pad (halfs)
constexpr int ASZ  = 128 * LDA;       // halfs per A stage = 5120
constexpr int BSZ  = KC * LDB;        // halfs per B stage = 8448
constexpr int STG  = ASZ + BSZ;       // 13568 halfs
constexpr int NSTAGE = 4;
constexpr int GEMM_SMEM = STG * 2 * NSTAGE;   // 108544 bytes
}

// ---- scratch (device globals) ---------------------------------------------
__device__ float  g_cur [Mn * Hn];
__device__ __align__(16) __half g_curP[(size_t)Mn * KA];
__device__ __align__(16) __half g_ctxP[(size_t)Mn * KA];
__device__ __align__(16) __half g_BT  [6 * (size_t)KTB * Hn];
__device__ float  g_Q   [Mn * Hn];
__device__ float  g_Kc  [Mn * Hn];
__device__ float  g_Vc  [Mn * Hn];
__device__ float  g_Kx  [Mn * Hn];
__device__ float  g_Vx  [Mn * Hn];
__device__ float  g_tmp [Mn * Hn];
__device__ float  g_Krel[Mn * Hn];
__device__ float  g_Vrel[Mn * Hn];

__device__ float g_center[Bn * Hn];
__device__ float g_Kcen [Bn * Hn];
__device__ float g_Vcen [Bn * Hn];
__device__ float g_Qrel [Bn * Hn];
__device__ float g_Krel0[Bn * Hn];
__device__ float g_Vrel0[Bn * Hn];
__device__ float g_relctx[Bn * Hn];
__device__ float g_cpart[Bn * 16 * Hn];

__device__ float g_pm[512];
__device__ float g_ps[512];
__device__ float g_pacc[512 * HDn];

// ---------------------------------------------------------------------------
// helpers
// ---------------------------------------------------------------------------
__device__ __forceinline__ uint32_t smem_u32(const void* p) {
    uint32_t a;
    asm("{ .reg .u64 t; cvta.to.shared.u64 t, %1; cvt.u32.u64 %0, t; }"
        : "=r"(a) : "l"(p));
    return a;
}
__device__ __forceinline__ void cp16(uint32_t s, const void* g) {
    asm volatile("cp.async.cg.shared.global [%0], [%1], 16;" :: "r"(s), "l"(g));
}
__device__ __forceinline__ void cp_commit() {
    asm volatile("cp.async.commit_group;" ::: "memory");
}
__device__ __forceinline__ void ldm_x4(uint32_t* r, uint32_t a) {
    asm volatile("ldmatrix.sync.aligned.m8n8.x4.shared.b16 {%0,%1,%2,%3}, [%4];"
                 : "=r"(r[0]), "=r"(r[1]), "=r"(r[2]), "=r"(r[3]) : "r"(a));
}
__device__ __forceinline__ void ldm_x4t(uint32_t* r, uint32_t a) {
    asm volatile("ldmatrix.sync.aligned.m8n8.x4.trans.shared.b16 {%0,%1,%2,%3}, [%4];"
                 : "=r"(r[0]), "=r"(r[1]), "=r"(r[2]), "=r"(r[3]) : "r"(a));
}
__device__ __forceinline__ void mma16816(float* c, const uint32_t* a,
                                         const uint32_t* b) {
    asm volatile(
        "mma.sync.aligned.m16n8k16.row.col.f32.f16.f16.f32 "
        "{%0,%1,%2,%3}, {%4,%5,%6,%7}, {%8,%9}, {%0,%1,%2,%3};"
        : "+f"(c[0]), "+f"(c[1]), "+f"(c[2]), "+f"(c[3])
        : "r"(a[0]), "r"(a[1]), "r"(a[2]), "r"(a[3]), "r"(b[0]), "r"(b[1]));
}
__device__ __forceinline__ void split_pair(float v, __half& hi, __half& lo) {
    hi = __float2half_rn(v);
    lo = __float2half_rn(v - __half2float(hi));
}

// ---------------------------------------------------------------------------
// GEMM: C[M,256] = (A' over K'=768) @ B'[768,256] * (1/256) + bias
// CTA 128(M) x 256(N, full), 8 warps at 64x64, KC=32, 4-stage cp.async.
// ---------------------------------------------------------------------------
__global__ __launch_bounds__(256, 1)
void hgemm_split(const __half* __restrict__ Ap, const __half* __restrict__ Bp,
                 const float* __restrict__ bias, float* __restrict__ C) {
    extern __shared__ __align__(16) __half smh[];
    const int tid = threadIdx.x;
    const int bm = blockIdx.x * 128;
    const uint32_t sbase = smem_u32(smh);

    auto load_chunk = [&](int j, int s) {
        const uint32_t st = sbase + (uint32_t)(s * STG) * 2;
        const int ka = (j < 16) ? j * KC : (j - 16) * KC;   // fold 3rd pass onto ah
#pragma unroll
        for (int i = 0; i < 2; i++) {                        // A: 512 16B segs
            int seg = tid + i * 256;
            int r = seg >> 2, c = seg & 3;
            cp16(st + (uint32_t)(r * LDA + c * 8) * 2,
                 Ap + (size_t)(bm + r) * KA + ka + c * 8);
        }
#pragma unroll
        for (int i = 0; i < 4; i++) {                        // B: 1024 16B segs
            int seg = tid + i * 256;
            int r = seg >> 5, c = seg & 31;
            cp16(st + (uint32_t)(ASZ + r * LDB + c * 8) * 2,
                 Bp + (size_t)(j * KC + r) * Hn + c * 8);
        }
        cp_commit();
    };

    const int warp = tid >> 5, lane = tid & 31;
    const int wm = (warp & 1) * 64;
    const int wn = (warp >> 1) * 64;
    const int lr = lane & 15;
    const int lg8 = (lane >> 4) * 8;

    float acc[4][8][4];
#pragma unroll
    for (int mi = 0; mi < 4; mi++)
#pragma unroll
        for (int ni = 0; ni < 8; ni++)
#pragma unroll
            for (int k = 0; k < 4; k++) acc[mi][ni][k] = 0.f;

    load_chunk(0, 0);
    load_chunk(1, 1);
    load_chunk(2, 2);

    for (int j = 0; j < NC; j++) {
        asm volatile("cp.async.wait_group 2;" ::: "memory");
        __syncthreads();
        if (j + 3 < NC) load_chunk(j + 3, (j + 3) & 3);
        else            cp_commit();                 // keep group depth constant

        const uint32_t st = sbase + (uint32_t)((j & 3) * STG) * 2;
#pragma unroll
        for (int ks = 0; ks < KC; ks += 16) {
            uint32_t a[4][4];
#pragma unroll
            for (int mi = 0; mi < 4; mi++)
                ldm_x4(a[mi], st + (uint32_t)((wm + mi * 16 + lr) * LDA + ks + lg8) * 2);
            uint32_t b[4][4];
#pragma unroll
            for (int np = 0; np < 4; np++)
                ldm_x4t(b[np], st + (uint32_t)(ASZ + (ks + lr) * LDB
                                               + wn + np * 16 + lg8) * 2);
#pragma unroll
            for (int mi = 0; mi < 4; mi++)
#pragma unroll
                for (int ni = 0; ni < 8; ni++)
                    mma16816(acc[mi][ni], a[mi], &b[ni >> 1][(ni & 1) * 2]);
        }
    }

    // epilogue: *1/256 + bias
    const int g = lane >> 2, tg = (lane & 3) * 2;
#pragma unroll
    for (int mi = 0; mi < 4; mi++) {
#pragma unroll
        for (int ni = 0; ni < 8; ni++) {
            int row = bm + wm + mi * 16 + g;
            int col = wn + ni * 8 + tg;
            float b0 = bias[col], b1 = bias[col + 1];
            float2 o0 = { acc[mi][ni][0] * INVW + b0, acc[mi][ni][1] * INVW + b1 };
            float2 o1 = { acc[mi][ni][2] * INVW + b0, acc[mi][ni][3] * INVW + b1 };
            *(float2*)(C + (size_t)row * Hn + col) = o0;
            *(float2*)(C + (size_t)(row + 8) * Hn + col) = o1;
        }
    }
}

// ---------------------------------------------------------------------------
// weight prep (all 6 weights in one launch): B'[768,256], rows k=bh, 256+k=bh,
// 512+k=bl, with W pre-scaled by 256.
// ---------------------------------------------------------------------------
__global__ void wprep_kernel(const float* W0, const float* W1, const float* W2,
                             const float* W3, const float* W4, const float* W5) {
    const float* Ws[6] = {W0, W1, W2, W3, W4, W5};
    int wi = blockIdx.y;
    int k = blockIdx.x, n = threadIdx.x;
    __half* Bp = g_BT + (size_t)wi * KTB * Hn;
    float w = Ws[wi][(size_t)k * Hn + n] * 256.f;
    __half bh, bl;
    split_pair(w, bh, bl);
    Bp[(size_t)k * Hn + n]                = bh;
    Bp[(size_t)(256 + k) * Hn + n]        = bh;
    Bp[(size_t)(512 + k) * Hn + n]        = bl;
}

// ---------------------------------------------------------------------------
// x -> cur (fp32) + curP (ah|al). Thread = 8 consecutive k of one row.
// ---------------------------------------------------------------------------
__global__ void splitcopy_kernel(const float* __restrict__ x) {
    int t = blockIdx.x * blockDim.x + threadIdx.x;   // Mn*Hn/8
    int row = t >> 5;
    int k0 = (t & 31) * 8;
    const float4* src = (const float4*)(x + (size_t)row * Hn + k0);
    float4* dst = (float4*)(g_cur + (size_t)row * Hn + k0);
    float4 v0 = src[0], v1 = src[1];
    dst[0] = v0; dst[1] = v1;
    __half hi[8], lo[8];
    float vv[8] = {v0.x, v0.y, v0.z, v0.w, v1.x, v1.y, v1.z, v1.w};
#pragma unroll
    for (int j = 0; j < 8; j++) split_pair(vv[j], hi[j], lo[j]);
    *(uint4*)(g_curP + (size_t)row * KA + k0)       = *(uint4*)hi;
    *(uint4*)(g_curP + (size_t)row * KA + 256 + k0) = *(uint4*)lo;
}

__global__ void copyf4_kernel(const float4* __restrict__ src,
                              float4* __restrict__ dst, int n4) {
    int i = blockIdx.x * blockDim.x + threadIdx.x;
    if (i < n4) dst[i] = src[i];
}
__global__ void copy_center_out_kernel(float* __restrict__ dst) {
    int i = blockIdx.x * blockDim.x + threadIdx.x;
    dst[i] = g_center[i];
}

// center = mean over L of x, two stages
__global__ void meanpart_kernel(const float* __restrict__ x) {
    int c = blockIdx.x, b = blockIdx.y, h = threadIdx.x;
    const float* p = x + ((size_t)b * Ln + c * 256) * Hn + h;
    float s = 0.f;
    for (int l = 0; l < 256; l++) s += p[(size_t)l * Hn];
    g_cpart[(b * 16 + c) * Hn + h] = s;
}
__global__ void meancomb_kernel() {
    int b = blockIdx.x, h = threadIdx.x;
    float s = 0.f;
    for (int c = 0; c < 16; c++) s += g_cpart[(b * 16 + c) * Hn + h];
    g_center[b * Hn + h] = s * (1.f / Ln);
}

// ---------------------------------------------------------------------------
// center projections (tiny fp32)
// ---------------------------------------------------------------------------
__global__ void proj_center_kernel(
    const float* __restrict__ satWk, const float* __restrict__ satbk,
    const float* __restrict__ satWv, const float* __restrict__ satbv,
    const float* __restrict__ relWq, const float* __restrict__ relbq,
    const float* __restrict__ relWk, const float* __restrict__ relbk,
    const float* __restrict__ relWv, const float* __restrict__ relbv) {
    __shared__ float c[Hn];
    int b   = blockIdx.x % Bn;
    int sel = blockIdx.x / Bn;
    int n   = threadIdx.x;
    c[n] = g_center[b * Hn + n];
    __syncthreads();
    const float* W; const float* bi; float* out;
    switch (sel) {
        case 0: W = satWk; bi = satbk; out = g_Kcen;  break;
        case 1: W = satWv; bi = satbv; out = g_Vcen;  break;
        case 2: W = relWq; bi = relbq; out = g_Qrel;  break;
        case 3: W = relWk; bi = relbk; out = g_Krel0; break;
        default: W = relWv; bi = relbv; out = g_Vrel0; break;
    }
    float s = 0.f;
#pragma unroll 8
    for (int k = 0; k < Hn; k++) s += c[k] * W[k * Hn + n];
    out[b * Hn + n] = s + bi[n];
}

// ---------------------------------------------------------------------------
// satellite attention -> writes ctx pair (ah|al)
// ---------------------------------------------------------------------------
__global__ __launch_bounds__(256)
void sat_attn_kernel(const float* __restrict__ Kc, const float* __restrict__ Vc) {
    int token = blockIdx.x;
    int b = token >> 12;
    int l = token & (Ln - 1);
    int h = threadIdx.x >> 5;
    int d = threadIdx.x & 31;
    int col = h * HDn + d;

    size_t ic   = (size_t)token * Hn + col;
    int lb = (l + 1) & (Ln - 1);
    int la = (l == 0) ? (Ln - 1) : 0;
    size_t ibe  = ((size_t)(b * Ln + lb)) * Hn + col;
    size_t iaf  = ((size_t)(b * Ln + la)) * Hn + col;
    size_t icen = (size_t)b * Hn + col;

    float q  = g_Q[ic];
    float s0 = q * Kc[ibe];
    float s1 = q * Kc[ic];
    float s2 = q * Kc[iaf];
    float s3 = q * g_Kx[ic];
    float s4 = q * g_Kcen[icen];
#pragma unroll
    for (int off = 16; off; off >>= 1) {
        s0 += __shfl_xor_sync(0xffffffffu, s0, off);
        s1 += __shfl_xor_sync(0xffffffffu, s1, off);
        s2 += __shfl_xor_sync(0xffffffffu, s2, off);
        s3 += __shfl_xor_sync(0xffffffffu, s3, off);
        s4 += __shfl_xor_sync(0xffffffffu, s4, off);
    }
    s0 *= SCALE; s1 *= SCALE; s2 *= SCALE; s3 *= SCALE; s4 *= SCALE;
    float mx = fmaxf(fmaxf(fmaxf(s0, s1), fmaxf(s2, s3)), s4);
    float e0 = expf(s0 - mx), e1 = expf(s1 - mx), e2 = expf(s2 - mx);
    float e3 = expf(s3 - mx), e4 = expf(s4 - mx);
    float inv = 1.f / (e0 + e1 + e2 + e3 + e4);
    float ctx = (e0 * Vc[ibe] + e1 * Vc[ic] + e2 * Vc[iaf] +
                 e3 * g_Vx[ic] + e4 * g_Vcen[icen]) * inv;

    __half ah, al;
    split_pair(ctx, ah, al);
    g_ctxP[(size_t)token * KA + col]       = ah;
    g_ctxP[(size_t)token * KA + 256 + col] = al;
}

// ---------------------------------------------------------------------------
// LN(relu(tmp + cur)) -> cur + curP, warp per row (no block syncs)
// ---------------------------------------------------------------------------
__global__ __launch_bounds__(256)
void ln_rows_kernel(const float* __restrict__ tmp, float* __restrict__ cur,
                    const float* __restrict__ w, const float* __restrict__ bvec) {
    int warp = threadIdx.x >> 5;
    int lane = threadIdx.x & 31;
    int row = blockIdx.x * 8 + warp;
    int k0 = lane * 8;
    size_t base = (size_t)row * Hn + k0;

    float4 t0 = *(const float4*)(tmp + base);
    float4 t1 = *(const float4*)(tmp + base + 4);
    float4 c0 = *(const float4*)(cur + base);
    float4 c1 = *(const float4*)(cur + base + 4);
    float v[8] = { fmaxf(t0.x + c0.x, 0.f), fmaxf(t0.y + c0.y, 0.f),
                   fmaxf(t0.z + c0.z, 0.f), fmaxf(t0.w + c0.w, 0.f),
                   fmaxf(t1.x + c1.x, 0.f), fmaxf(t1.y + c1.y, 0.f),
                   fmaxf(t1.z + c1.z, 0.f), fmaxf(t1.w + c1.w, 0.f) };

    float s = 0.f;
#pragma unroll
    for (int j = 0; j < 8; j++) s += v[j];
#pragma unroll
    for (int off = 16; off; off >>= 1) s += __shfl_xor_sync(0xffffffffu, s, off);
    float mean = s * (1.f / Hn);

    float s2 = 0.f;
#pragma unroll
    for (int j = 0; j < 8; j++) { float d = v[j] - mean; s2 += d * d; }
#pragma unroll
    for (int off = 16; off; off >>= 1) s2 += __shfl_xor_sync(0xffffffffu, s2, off);
    float rstd = rsqrtf(s2 * (1.f / Hn) + LNEPS);

    float4 w0 = *(const float4*)(w + k0);
    float4 w1 = *(const float4*)(w + k0 + 4);
    float4 b0 = *(const float4*)(bvec + k0);
    float4 b1 = *(const float4*)(bvec + k0 + 4);
    float ww[8] = {w0.x, w0.y, w0.z, w0.w, w1.x, w1.y, w1.z, w1.w};
    float bb[8] = {b0.x, b0.y, b0.z, b0.w, b1.x, b1.y, b1.z, b1.w};

    float o[8];
    __half hi[8], lo[8];
#pragma unroll
    for (int j = 0; j < 8; j++) {
        o[j] = ww[j] * (v[j] - mean) * rstd + bb[j];
        split_pair(o[j], hi[j], lo[j]);
    }
    *(float4*)(cur + base)     = make_float4(o[0], o[1], o[2], o[3]);
    *(float4*)(cur + base + 4) = make_float4(o[4], o[5], o[6], o[7]);
    *(uint4*)(g_curP + (size_t)row * KA + k0)       = *(uint4*)hi;
    *(uint4*)(g_curP + (size_t)row * KA + 256 + k0) = *(uint4*)lo;
}

// ---------------------------------------------------------------------------
// relay attention split-KV (512 blocks) + combine
// ---------------------------------------------------------------------------
__global__ __launch_bounds__(256)
void rel_part_kernel() {
    __shared__ float qs[HDn];
    __shared__ float sm[256], ss[256];
    __shared__ float sacc[256 * HDn];

    int bh = blockIdx.x >> 3;
    int sp = blockIdx.x & 7;
    int b = bh >> 3, h = bh & 7;
    int t = threadIdx.x;

    if (t < HDn) qs[t] = g_Qrel[b * Hn + h * HDn + t];
    __syncthreads();

    float m = -1e30f, ssum = 0.f;
    float acc[HDn];
#pragma unroll
    for (int d = 0; d < HDn; d++) acc[d] = 0.f;

    for (int j = sp * 256 + t; j <= Ln; j += 2048) {
        const float* kv; const float* vv;
        if (j == 0) {
            kv = g_Krel0 + b * Hn + h * HDn;
            vv = g_Vrel0 + b * Hn + h * HDn;
        } else {
            size_t base = ((size_t)(b * Ln + j - 1)) * Hn + h * HDn;
            kv = g_Krel + base;
            vv = g_Vrel + base;
        }
        float s = 0.f;
#pragma unroll
        for (int d = 0; d < HDn; d += 4) {
            float4 k4 = *(const float4*)(kv + d);
            s += qs[d] * k4.x + qs[d + 1] * k4.y + qs[d + 2] * k4.z + qs[d + 3] * k4.w;
        }
        s *= SCALE;
        float mn = fmaxf(m, s);
        float corr = expf(m - mn);
        float p = expf(s - mn);
        ssum = ssum * corr + p;
#pragma unroll
        for (int d = 0; d < HDn; d += 4) {
            float4 v4 = *(const float4*)(vv + d);
            acc[d + 0] = acc[d + 0] * corr + p * v4.x;
            acc[d + 1] = acc[d + 1] * corr + p * v4.y;
            acc[d + 2] = acc[d + 2] * corr + p * v4.z;
            acc[d + 3] = acc[d + 3] * corr + p * v4.w;
        }
        m = mn;
    }

    sm[t] = m; ss[t] = ssum;
#pragma unroll
    for (int d = 0; d < HDn; d++) sacc[t * HDn + d] = acc[d];
    __syncthreads();

    for (int stride = 128; stride > 0; stride >>= 1) {
        if (t < stride) {
            float m1 = sm[t], m2 = sm[t + stride];
            float mn = fmaxf(m1, m2);
            float c1 = expf(m1 - mn), c2 = expf(m2 - mn);
            sm[t] = mn;
            ss[t] = ss[t] * c1 + ss[t + stride] * c2;
            for (int d = 0; d < HDn; d++)
                sacc[t * HDn + d] = sacc[t * HDn + d] * c1 + sacc[(t + stride) * HDn + d] * c2;
        }
        __syncthreads();
    }

    if (t == 0) { g_pm[blockIdx.x] = sm[0]; g_ps[blockIdx.x] = ss[0]; }
    if (t < HDn) g_pacc[blockIdx.x * HDn + t] = sacc[t];
}

__global__ void rel_comb_kernel() {   // grid 64, 32 threads
    int bh = blockIdx.x;
    int d = threadIdx.x;
    float m = -1e30f;
#pragma unroll
    for (int sp = 0; sp < 8; sp++) m = fmaxf(m, g_pm[bh * 8 + sp]);
    float s = 0.f, a = 0.f;
#pragma unroll
    for (int sp = 0; sp < 8; sp++) {
        float c = expf(g_pm[bh * 8 + sp] - m);
        s += g_ps[bh * 8 + sp] * c;
        a += g_pacc[(bh * 8 + sp) * HDn + d] * c;
    }
    g_relctx[bh * HDn + d] = a / s;
}

// ---------------------------------------------------------------------------
// relay epilogue: center = LN(relu(relctx @ Wo + bo + center))
// ---------------------------------------------------------------------------
__global__ __launch_bounds__(256)
void rel_epi_kernel(const float* __restrict__ Wo, const float* __restrict__ bo,
                    const float* __restrict__ lnw, const float* __restrict__ lnb) {
    __shared__ float cx[Hn];
    __shared__ float red[8];
    int b = blockIdx.x;
    int n = threadIdx.x;
    cx[n] = g_relctx[b * Hn + n];
    float resid = g_center[b * Hn + n];
    __syncthreads();
    float s = 0.f;
#pragma unroll 8
    for (int k = 0; k < Hn; k++) s += cx[k] * Wo[k * Hn + n];
    float v = fmaxf(s + bo[n] + resid, 0.f);

    float r = v;
#pragma unroll
    for (int off = 16; off; off >>= 1) r += __shfl_xor_sync(0xffffffffu, r, off);
    if ((n & 31) == 0) red[n >> 5] = r;
    __syncthreads();
    float tot = 0.f;
#pragma unroll
    for (int i = 0; i < 8; i++) tot += red[i];
    float mean = tot * (1.f / Hn);
    __syncthreads();

    float dv = v - mean;
    float r2 = dv * dv;
#pragma unroll
    for (int off = 16; off; off >>= 1) r2 += __shfl_xor_sync(0xffffffffu, r2, off);
    if ((n & 31) == 0) red[n >> 5] = r2;
    __syncthreads();
    tot = 0.f;
#pragma unroll
    for (int i = 0; i < 8; i++) tot += red[i];
    float var = tot * (1.f / Hn);

    g_center[b * Hn + n] = lnw[n] * dv * rsqrtf(var + LNEPS) + lnb[n];
}

// ---------------------------------------------------------------------------
extern "C" void kernel_launch(void* const* d_in, const int* in_sizes, int n_in,
                              void* d_out, int out_size) {
    const float* x     = (const float*)d_in[0];
    const float* satWq = (const float*)d_in[1];  const float* satbq = (const float*)d_in[2];
    const float* satWk = (const float*)d_in[3];  const float* satbk = (const float*)d_in[4];
    const float* satWv = (const float*)d_in[5];  const float* satbv = (const float*)d_in[6];
    const float* satWo = (const float*)d_in[7];  const float* satbo = (const float*)d_in[8];
    const float* relWq = (const float*)d_in[9];  const float* relbq = (const float*)d_in[10];
    const float* relWk = (const float*)d_in[11]; const float* relbk = (const float*)d_in[12];
    const float* relWv = (const float*)d_in[13]; const float* relbv = (const float*)d_in[14];
    const float* relWo = (const float*)d_in[15]; const float* relbo = (const float*)d_in[16];
    const float* slnw  = (const float*)d_in[17]; const float* slnb  = (const float*)d_in[18];
    const float* rlnw  = (const float*)d_in[19]; const float* rlnb  = (const float*)d_in[20];
    float* out = (float*)d_out;

    float *cur, *Q, *Kc, *Vc, *Kx, *Vx, *tmp, *Krel, *Vrel;
    __half *curP, *ctxP, *BT;
    cudaGetSymbolAddress((void**)&cur,  g_cur);
    cudaGetSymbolAddress((void**)&Q,    g_Q);
    cudaGetSymbolAddress((void**)&Kc,   g_Kc);
    cudaGetSymbolAddress((void**)&Vc,   g_Vc);
    cudaGetSymbolAddress((void**)&Kx,   g_Kx);
    cudaGetSymbolAddress((void**)&Vx,   g_Vx);
    cudaGetSymbolAddress((void**)&tmp,  g_tmp);
    cudaGetSymbolAddress((void**)&Krel, g_Krel);
    cudaGetSymbolAddress((void**)&Vrel, g_Vrel);
    cudaGetSymbolAddress((void**)&curP, g_curP);
    cudaGetSymbolAddress((void**)&ctxP, g_ctxP);
    cudaGetSymbolAddress((void**)&BT,   g_BT);

    cudaFuncSetAttribute(hgemm_split, cudaFuncAttributeMaxDynamicSharedMemorySize,
                         GEMM_SMEM);

    // weight prep: 0 satWq, 1 satWk, 2 satWv, 3 satWo, 4 relWk, 5 relWv
    wprep_kernel<<<dim3(Hn, 6), Hn>>>(satWq, satWk, satWv, satWo, relWk, relWv);

    splitcopy_kernel<<<Mn * Hn / 8 / 256, 256>>>(x);
    meanpart_kernel<<<dim3(16, Bn), Hn>>>(x);
    meancomb_kernel<<<Bn, Hn>>>();

    #define GEMM(AT, WI, BIAS, CPTR) \
        hgemm_split<<<Mn / 128, 256, GEMM_SMEM>>>(AT, BT + (size_t)(WI) * KTB * Hn, \
                                                  BIAS, CPTR)

    for (int it = 0; it < 2; it++) {
        proj_center_kernel<<<5 * Bn, Hn>>>(satWk, satbk, satWv, satbv,
                                           relWq, relbq, relWk, relbk, relWv, relbv);
        GEMM(curP, 0, satbq, Q);
        // iter 0: cur == x, so Kc/Vc double as the loop-invariant Kx/Vx
        float* Kdst = (it == 0) ? Kx : Kc;
        float* Vdst = (it == 0) ? Vx : Vc;
        GEMM(curP, 1, satbk, Kdst);
        GEMM(curP, 2, satbv, Vdst);
        sat_attn_kernel<<<Mn, 256>>>(Kdst, Vdst);
        GEMM(ctxP, 3, satbo, tmp);
        ln_rows_kernel<<<Mn / 8, 256>>>(tmp, cur, slnw, slnb);
        GEMM(curP, 4, relbk, Krel);
        GEMM(curP, 5, relbv, Vrel);
        rel_part_kernel<<<Bn * NHn * 8, 256>>>();
        rel_comb_kernel<<<Bn * NHn, HDn>>>();
        rel_epi_kernel<<<Bn, Hn>>>(relWo, relbo, rlnw, rlnb);
    }
    #undef GEMM

    const int n4 = Mn * Hn / 4;
    copyf4_kernel<<<(n4 + 255) / 256, 256>>>((const float4*)cur, (float4*)out, n4);
    copy_center_out_kernel<<<Bn, Hn>>>(out + (size_t)Mn * Hn);
}

// round 7
// speedup vs baseline: 2.5487x; 1.2272x over previous
#include <cuda_runtime.h>
#include <cuda_fp16.h>
#include <math.h>
#include <stdint.h>

// ---------------------------------------------------------------------------
// StarTransformerLayer, GB300 (compute_103 -> mma.sync path).
// B=8, L=4096, H=256, NH=8, HD=32, 2 iterations.
// GEMMs: fp16 2-term split. A' = [ah | al] (K'=512). B' = bh only [256x256];
// GEMM pairs A chunk j with B chunk (j&7): computes (ah+al)*bh in one pass.
// Dropped a*bl term -> ~1e-4 relative error (W fp16 rounding), fp32 accum.
// ---------------------------------------------------------------------------

namespace {
constexpr int Bn  = 8;
constexpr int Ln  = 4096;
constexpr int Hn  = 256;
constexpr int NHn = 8;
constexpr int HDn = 32;
constexpr int Mn  = Bn * Ln;          // 32768
constexpr int KA  = 512;              // stored A' columns (ah | al)
constexpr float SCALE = 0.17677669529663688f;   // 1/sqrt(32)
constexpr float LNEPS = 1e-12f;
// GEMM tiling
constexpr int KC   = 32;
constexpr int NC   = KA / KC;         // 16 chunks
constexpr int LDA  = 40;              // 32 + 8 pad (halfs)
constexpr int LDB  = 264;             // 256 + 8 pad (halfs)
constexpr int ASZ  = 128 * LDA;       // 5120 halfs
constexpr int BSZ  = KC * LDB;        // 8448 halfs
constexpr int STG  = ASZ + BSZ;       // 13568 halfs
constexpr int GEMM_SMEM = STG * 2 * 4;   // 108544 bytes (4 stages)
}

// ---- scratch (device globals) ---------------------------------------------
__device__ float  g_cur [Mn * Hn];
__device__ __align__(16) __half g_curP[(size_t)Mn * KA];
__device__ __align__(16) __half g_ctxP[(size_t)Mn * KA];
__device__ __align__(16) __half g_BT  [6 * (size_t)Hn * Hn];   // bh per weight
__device__ float  g_Q   [Mn * Hn];
__device__ float  g_Kc  [Mn * Hn];
__device__ float  g_Vc  [Mn * Hn];
__device__ float  g_Kx  [Mn * Hn];
__device__ float  g_Vx  [Mn * Hn];
__device__ float  g_tmp [Mn * Hn];
__device__ float  g_Krel[Mn * Hn];
__device__ float  g_Vrel[Mn * Hn];

__device__ float g_center[Bn * Hn];
__device__ float g_Kcen [Bn * Hn];
__device__ float g_Vcen [Bn * Hn];
__device__ float g_Qrel [Bn * Hn];
__device__ float g_Krel0[Bn * Hn];
__device__ float g_Vrel0[Bn * Hn];
__device__ float g_cpart[Bn * 16 * Hn];

__device__ float g_pm[512];
__device__ float g_ps[512];
__device__ float g_pacc[512 * HDn];

// ---------------------------------------------------------------------------
// helpers
// ---------------------------------------------------------------------------
__device__ __forceinline__ uint32_t smem_u32(const void* p) {
    uint32_t a;
    asm("{ .reg .u64 t; cvta.to.shared.u64 t, %1; cvt.u32.u64 %0, t; }"
        : "=r"(a) : "l"(p));
    return a;
}
__device__ __forceinline__ void cp16(uint32_t s, const void* g) {
    asm volatile("cp.async.cg.shared.global [%0], [%1], 16;" :: "r"(s), "l"(g));
}
__device__ __forceinline__ void cp_commit() {
    asm volatile("cp.async.commit_group;" ::: "memory");
}
__device__ __forceinline__ void ldm_x4(uint32_t* r, uint32_t a) {
    asm volatile("ldmatrix.sync.aligned.m8n8.x4.shared.b16 {%0,%1,%2,%3}, [%4];"
                 : "=r"(r[0]), "=r"(r[1]), "=r"(r[2]), "=r"(r[3]) : "r"(a));
}
__device__ __forceinline__ void ldm_x4t(uint32_t* r, uint32_t a) {
    asm volatile("ldmatrix.sync.aligned.m8n8.x4.trans.shared.b16 {%0,%1,%2,%3}, [%4];"
                 : "=r"(r[0]), "=r"(r[1]), "=r"(r[2]), "=r"(r[3]) : "r"(a));
}
__device__ __forceinline__ void mma16816(float* c, const uint32_t* a,
                                         const uint32_t* b) {
    asm volatile(
        "mma.sync.aligned.m16n8k16.row.col.f32.f16.f16.f32 "
        "{%0,%1,%2,%3}, {%4,%5,%6,%7}, {%8,%9}, {%0,%1,%2,%3};"
        : "+f"(c[0]), "+f"(c[1]), "+f"(c[2]), "+f"(c[3])
        : "r"(a[0]), "r"(a[1]), "r"(a[2]), "r"(a[3]), "r"(b[0]), "r"(b[1]));
}
__device__ __forceinline__ void split_pair(float v, __half& hi, __half& lo) {
    hi = __float2half_rn(v);
    lo = __float2half_rn(v - __half2float(hi));
}

// ---------------------------------------------------------------------------
// GEMM: C[M,256] = A'[M,512] @ [bh;bh] + bias.  CTA 128x256, 8 warps 64x64,
// KC=32, 4-stage cp.async. blockIdx.y selects (B, bias, C) from up to 3 sets.
// ---------------------------------------------------------------------------
__global__ __launch_bounds__(256, 1)
void hgemm2(const __half* __restrict__ Ap,
            const __half* B0, const __half* B1, const __half* B2,
            const float* bias0, const float* bias1, const float* bias2,
            float* C0, float* C1, float* C2) {
    extern __shared__ __align__(16) __half smh[];
    const int tid = threadIdx.x;
    const int bm = blockIdx.x * 128;
    const int wsel = blockIdx.y;
    const __half* Bp  = (wsel == 0) ? B0 : (wsel == 1) ? B1 : B2;
    const float*  bias = (wsel == 0) ? bias0 : (wsel == 1) ? bias1 : bias2;
    float*        C   = (wsel == 0) ? C0 : (wsel == 1) ? C1 : C2;
    const uint32_t sbase = smem_u32(smh);

    auto load_chunk = [&](int j, int s) {
        const uint32_t st = sbase + (uint32_t)(s * STG) * 2;
        const int kb = (j & 7) * KC;          // B folds onto bh
#pragma unroll
        for (int i = 0; i < 2; i++) {          // A: 512 16B segs
            int seg = tid + i * 256;
            int r = seg >> 2, c = seg & 3;
            cp16(st + (uint32_t)(r * LDA + c * 8) * 2,
                 Ap + (size_t)(bm + r) * KA + j * KC + c * 8);
        }
#pragma unroll
        for (int i = 0; i < 4; i++) {          // B: 1024 16B segs
            int seg = tid + i * 256;
            int r = seg >> 5, c = seg & 31;
            cp16(st + (uint32_t)(ASZ + r * LDB + c * 8) * 2,
                 Bp + (size_t)(kb + r) * Hn + c * 8);
        }
        cp_commit();
    };

    const int warp = tid >> 5, lane = tid & 31;
    const int wm = (warp & 1) * 64;
    const int wn = (warp >> 1) * 64;
    const int lr = lane & 15;
    const int lg8 = (lane >> 4) * 8;

    float acc[4][8][4];
#pragma unroll
    for (int mi = 0; mi < 4; mi++)
#pragma unroll
        for (int ni = 0; ni < 8; ni++)
#pragma unroll
            for (int k = 0; k < 4; k++) acc[mi][ni][k] = 0.f;

    load_chunk(0, 0);
    load_chunk(1, 1);
    load_chunk(2, 2);

    for (int j = 0; j < NC; j++) {
        asm volatile("cp.async.wait_group 2;" ::: "memory");
        __syncthreads();
        if (j + 3 < NC) load_chunk(j + 3, (j + 3) & 3);
        else            cp_commit();           // constant group depth

        const uint32_t st = sbase + (uint32_t)((j & 3) * STG) * 2;
#pragma unroll
        for (int ks = 0; ks < KC; ks += 16) {
            uint32_t a[4][4];
#pragma unroll
            for (int mi = 0; mi < 4; mi++)
                ldm_x4(a[mi], st + (uint32_t)((wm + mi * 16 + lr) * LDA + ks + lg8) * 2);
            uint32_t b[4][4];
#pragma unroll
            for (int np = 0; np < 4; np++)
                ldm_x4t(b[np], st + (uint32_t)(ASZ + (ks + lr) * LDB
                                               + wn + np * 16 + lg8) * 2);
#pragma unroll
            for (int mi = 0; mi < 4; mi++)
#pragma unroll
                for (int ni = 0; ni < 8; ni++)
                    mma16816(acc[mi][ni], a[mi], &b[ni >> 1][(ni & 1) * 2]);
        }
    }

    const int g = lane >> 2, tg = (lane & 3) * 2;
#pragma unroll
    for (int mi = 0; mi < 4; mi++) {
#pragma unroll
        for (int ni = 0; ni < 8; ni++) {
            int row = bm + wm + mi * 16 + g;
            int col = wn + ni * 8 + tg;
            float b0 = bias[col], b1 = bias[col + 1];
            float2 o0 = { acc[mi][ni][0] + b0, acc[mi][ni][1] + b1 };
            float2 o1 = { acc[mi][ni][2] + b0, acc[mi][ni][3] + b1 };
            *(float2*)(C + (size_t)row * Hn + col) = o0;
            *(float2*)(C + (size_t)(row + 8) * Hn + col) = o1;
        }
    }
}

// ---------------------------------------------------------------------------
// weight prep: bh[256x256] per weight, all 6 in one launch
// ---------------------------------------------------------------------------
__global__ void wprep_kernel(const float* W0, const float* W1, const float* W2,
                             const float* W3, const float* W4, const float* W5) {
    const float* Ws[6] = {W0, W1, W2, W3, W4, W5};
    int wi = blockIdx.y;
    int k = blockIdx.x, n = threadIdx.x;
    g_BT[(size_t)wi * Hn * Hn + (size_t)k * Hn + n] =
        __float2half_rn(Ws[wi][(size_t)k * Hn + n]);
}

// ---------------------------------------------------------------------------
// x -> cur (fp32) + curP (ah|al)
// ---------------------------------------------------------------------------
__global__ void splitcopy_kernel(const float* __restrict__ x) {
    int t = blockIdx.x * blockDim.x + threadIdx.x;   // Mn*Hn/8
    int row = t >> 5;
    int k0 = (t & 31) * 8;
    const float4* src = (const float4*)(x + (size_t)row * Hn + k0);
    float4* dst = (float4*)(g_cur + (size_t)row * Hn + k0);
    float4 v0 = src[0], v1 = src[1];
    dst[0] = v0; dst[1] = v1;
    __half hi[8], lo[8];
    float vv[8] = {v0.x, v0.y, v0.z, v0.w, v1.x, v1.y, v1.z, v1.w};
#pragma unroll
    for (int j = 0; j < 8; j++) split_pair(vv[j], hi[j], lo[j]);
    *(uint4*)(g_curP + (size_t)row * KA + k0)       = *(uint4*)hi;
    *(uint4*)(g_curP + (size_t)row * KA + 256 + k0) = *(uint4*)lo;
}

// partial column sums of x over L (stage 1 of mean)
__global__ void meanpart_kernel(const float* __restrict__ x) {
    int c = blockIdx.x, b = blockIdx.y, h = threadIdx.x;
    const float* p = x + ((size_t)b * Ln + c * 256) * Hn + h;
    float s = 0.f;
    for (int l = 0; l < 256; l++) s += p[(size_t)l * Hn];
    g_cpart[(b * 16 + c) * Hn + h] = s;
}

// ---------------------------------------------------------------------------
// center projections; optionally finishes the mean (iter 0) and stores center
// ---------------------------------------------------------------------------
__global__ void proj_center_kernel(
    const float* __restrict__ satWk, const float* __restrict__ satbk,
    const float* __restrict__ satWv, const float* __restrict__ satbv,
    const float* __restrict__ relWq, const float* __restrict__ relbq,
    const float* __restrict__ relWk, const float* __restrict__ relbk,
    const float* __restrict__ relWv, const float* __restrict__ relbv,
    int use_cpart) {
    __shared__ float c[Hn];
    int b   = blockIdx.x % Bn;
    int sel = blockIdx.x / Bn;
    int n   = threadIdx.x;
    if (use_cpart) {
        float s = 0.f;
#pragma unroll
        for (int i = 0; i < 16; i++) s += g_cpart[(b * 16 + i) * Hn + n];
        float ctr = s * (1.f / Ln);
        c[n] = ctr;
        if (sel == 0) g_center[b * Hn + n] = ctr;
    } else {
        c[n] = g_center[b * Hn + n];
    }
    __syncthreads();
    const float* W; const float* bi; float* out;
    switch (sel) {
        case 0: W = satWk; bi = satbk; out = g_Kcen;  break;
        case 1: W = satWv; bi = satbv; out = g_Vcen;  break;
        case 2: W = relWq; bi = relbq; out = g_Qrel;  break;
        case 3: W = relWk; bi = relbk; out = g_Krel0; break;
        default: W = relWv; bi = relbv; out = g_Vrel0; break;
    }
    float s = 0.f;
#pragma unroll 8
    for (int k = 0; k < Hn; k++) s += c[k] * W[k * Hn + n];
    out[b * Hn + n] = s + bi[n];
}

// ---------------------------------------------------------------------------
// satellite attention -> writes ctx pair (ah|al)
// ---------------------------------------------------------------------------
__global__ __launch_bounds__(256)
void sat_attn_kernel(const float* __restrict__ Kc, const float* __restrict__ Vc) {
    int token = blockIdx.x;
    int b = token >> 12;
    int l = token & (Ln - 1);
    int h = threadIdx.x >> 5;
    int d = threadIdx.x & 31;
    int col = h * HDn + d;

    size_t ic   = (size_t)token * Hn + col;
    int lb = (l + 1) & (Ln - 1);
    int la = (l == 0) ? (Ln - 1) : 0;
    size_t ibe  = ((size_t)(b * Ln + lb)) * Hn + col;
    size_t iaf  = ((size_t)(b * Ln + la)) * Hn + col;
    size_t icen = (size_t)b * Hn + col;

    float q  = g_Q[ic];
    float s0 = q * Kc[ibe];
    float s1 = q * Kc[ic];
    float s2 = q * Kc[iaf];
    float s3 = q * g_Kx[ic];
    float s4 = q * g_Kcen[icen];
#pragma unroll
    for (int off = 16; off; off >>= 1) {
        s0 += __shfl_xor_sync(0xffffffffu, s0, off);
        s1 += __shfl_xor_sync(0xffffffffu, s1, off);
        s2 += __shfl_xor_sync(0xffffffffu, s2, off);
        s3 += __shfl_xor_sync(0xffffffffu, s3, off);
        s4 += __shfl_xor_sync(0xffffffffu, s4, off);
    }
    s0 *= SCALE; s1 *= SCALE; s2 *= SCALE; s3 *= SCALE; s4 *= SCALE;
    float mx = fmaxf(fmaxf(fmaxf(s0, s1), fmaxf(s2, s3)), s4);
    float e0 = expf(s0 - mx), e1 = expf(s1 - mx), e2 = expf(s2 - mx);
    float e3 = expf(s3 - mx), e4 = expf(s4 - mx);
    float inv = 1.f / (e0 + e1 + e2 + e3 + e4);
    float ctx = (e0 * Vc[ibe] + e1 * Vc[ic] + e2 * Vc[iaf] +
                 e3 * g_Vx[ic] + e4 * g_Vcen[icen]) * inv;

    __half ah, al;
    split_pair(ctx, ah, al);
    g_ctxP[(size_t)token * KA + col]       = ah;
    g_ctxP[(size_t)token * KA + 256 + col] = al;
}

// ---------------------------------------------------------------------------
// LN(relu(tmp + curIn)) -> outF (fp32) + curP, warp per row
// ---------------------------------------------------------------------------
__global__ __launch_bounds__(256)
void ln_rows_kernel(const float* __restrict__ tmp, const float* __restrict__ curIn,
                    float* __restrict__ outF,
                    const float* __restrict__ w, const float* __restrict__ bvec) {
    int warp = threadIdx.x >> 5;
    int lane = threadIdx.x & 31;
    int row = blockIdx.x * 8 + warp;
    int k0 = lane * 8;
    size_t base = (size_t)row * Hn + k0;

    float4 t0 = *(const float4*)(tmp + base);
    float4 t1 = *(const float4*)(tmp + base + 4);
    float4 c0 = *(const float4*)(curIn + base);
    float4 c1 = *(const float4*)(curIn + base + 4);
    float v[8] = { fmaxf(t0.x + c0.x, 0.f), fmaxf(t0.y + c0.y, 0.f),
                   fmaxf(t0.z + c0.z, 0.f), fmaxf(t0.w + c0.w, 0.f),
                   fmaxf(t1.x + c1.x, 0.f), fmaxf(t1.y + c1.y, 0.f),
                   fmaxf(t1.z + c1.z, 0.f), fmaxf(t1.w + c1.w, 0.f) };

    float s = 0.f;
#pragma unroll
    for (int j = 0; j < 8; j++) s += v[j];
#pragma unroll
    for (int off = 16; off; off >>= 1) s += __shfl_xor_sync(0xffffffffu, s, off);
    float mean = s * (1.f / Hn);

    float s2 = 0.f;
#pragma unroll
    for (int j = 0; j < 8; j++) { float d = v[j] - mean; s2 += d * d; }
#pragma unroll
    for (int off = 16; off; off >>= 1) s2 += __shfl_xor_sync(0xffffffffu, s2, off);
    float rstd = rsqrtf(s2 * (1.f / Hn) + LNEPS);

    float4 w0 = *(const float4*)(w + k0);
    float4 w1 = *(const float4*)(w + k0 + 4);
    float4 b0 = *(const float4*)(bvec + k0);
    float4 b1 = *(const float4*)(bvec + k0 + 4);
    float ww[8] = {w0.x, w0.y, w0.z, w0.w, w1.x, w1.y, w1.z, w1.w};
    float bb[8] = {b0.x, b0.y, b0.z, b0.w, b1.x, b1.y, b1.z, b1.w};

    float o[8];
    __half hi[8], lo[8];
#pragma unroll
    for (int j = 0; j < 8; j++) {
        o[j] = ww[j] * (v[j] - mean) * rstd + bb[j];
        split_pair(o[j], hi[j], lo[j]);
    }
    *(float4*)(outF + base)     = make_float4(o[0], o[1], o[2], o[3]);
    *(float4*)(outF + base + 4) = make_float4(o[4], o[5], o[6], o[7]);
    *(uint4*)(g_curP + (size_t)row * KA + k0)       = *(uint4*)hi;
    *(uint4*)(g_curP + (size_t)row * KA + 256 + k0) = *(uint4*)lo;
}

// ---------------------------------------------------------------------------
// relay attention split-KV (512 blocks)
// ---------------------------------------------------------------------------
__global__ __launch_bounds__(256)
void rel_part_kernel() {
    __shared__ float qs[HDn];
    __shared__ float sm[256], ss[256];
    __shared__ float sacc[256 * HDn];

    int bh = blockIdx.x >> 3;
    int sp = blockIdx.x & 7;
    int b = bh >> 3, h = bh & 7;
    int t = threadIdx.x;

    if (t < HDn) qs[t] = g_Qrel[b * Hn + h * HDn + t];
    __syncthreads();

    float m = -1e30f, ssum = 0.f;
    float acc[HDn];
#pragma unroll
    for (int d = 0; d < HDn; d++) acc[d] = 0.f;

    for (int j = sp * 256 + t; j <= Ln; j += 2048) {
        const float* kv; const float* vv;
        if (j == 0) {
            kv = g_Krel0 + b * Hn + h * HDn;
            vv = g_Vrel0 + b * Hn + h * HDn;
        } else {
            size_t base = ((size_t)(b * Ln + j - 1)) * Hn + h * HDn;
            kv = g_Krel + base;
            vv = g_Vrel + base;
        }
        float s = 0.f;
#pragma unroll
        for (int d = 0; d < HDn; d += 4) {
            float4 k4 = *(const float4*)(kv + d);
            s += qs[d] * k4.x + qs[d + 1] * k4.y + qs[d + 2] * k4.z + qs[d + 3] * k4.w;
        }
        s *= SCALE;
        float mn = fmaxf(m, s);
        float corr = expf(m - mn);
        float p = expf(s - mn);
        ssum = ssum * corr + p;
#pragma unroll
        for (int d = 0; d < HDn; d += 4) {
            float4 v4 = *(const float4*)(vv + d);
            acc[d + 0] = acc[d + 0] * corr + p * v4.x;
            acc[d + 1] = acc[d + 1] * corr + p * v4.y;
            acc[d + 2] = acc[d + 2] * corr + p * v4.z;
            acc[d + 3] = acc[d + 3] * corr + p * v4.w;
        }
        m = mn;
    }

    sm[t] = m; ss[t] = ssum;
#pragma unroll
    for (int d = 0; d < HDn; d++) sacc[t * HDn + d] = acc[d];
    __syncthreads();

    for (int stride = 128; stride > 0; stride >>= 1) {
        if (t < stride) {
            float m1 = sm[t], m2 = sm[t + stride];
            float mn = fmaxf(m1, m2);
            float c1 = expf(m1 - mn), c2 = expf(m2 - mn);
            sm[t] = mn;
            ss[t] = ss[t] * c1 + ss[t + stride] * c2;
            for (int d = 0; d < HDn; d++)
                sacc[t * HDn + d] = sacc[t * HDn + d] * c1 + sacc[(t + stride) * HDn + d] * c2;
        }
        __syncthreads();
    }

    if (t == 0) { g_pm[blockIdx.x] = sm[0]; g_ps[blockIdx.x] = ss[0]; }
    if (t < HDn) g_pacc[blockIdx.x * HDn + t] = sacc[t];
}

// ---------------------------------------------------------------------------
// relay epilogue (with split-KV combine folded in):
// dst_center = LN(relu(relctx @ Wo + bo + center))
// ---------------------------------------------------------------------------
__global__ __launch_bounds__(256)
void rel_epi_kernel(const float* __restrict__ Wo, const float* __restrict__ bo,
                    const float* __restrict__ lnw, const float* __restrict__ lnb,
                    float* __restrict__ dst) {
    __shared__ float cx[Hn];
    __shared__ float red[8];
    int b = blockIdx.x;
    int n = threadIdx.x;
    // combine 8 splits for (b, h=n>>5), dim d=n&31
    {
        int h = n >> 5, d = n & 31;
        int bh = b * 8 + h;
        float m = -1e30f;
#pragma unroll
        for (int sp = 0; sp < 8; sp++) m = fmaxf(m, g_pm[bh * 8 + sp]);
        float s = 0.f, a = 0.f;
#pragma unroll
        for (int sp = 0; sp < 8; sp++) {
            float c = expf(g_pm[bh * 8 + sp] - m);
            s += g_ps[bh * 8 + sp] * c;
            a += g_pacc[(bh * 8 + sp) * HDn + d] * c;
        }
        cx[n] = a / s;
    }
    float resid = g_center[b * Hn + n];
    __syncthreads();
    float s = 0.f;
#pragma unroll 8
    for (int k = 0; k < Hn; k++) s += cx[k] * Wo[k * Hn + n];
    float v = fmaxf(s + bo[n] + resid, 0.f);

    float r = v;
#pragma unroll
    for (int off = 16; off; off >>= 1) r += __shfl_xor_sync(0xffffffffu, r, off);
    if ((n & 31) == 0) red[n >> 5] = r;
    __syncthreads();
    float tot = 0.f;
#pragma unroll
    for (int i = 0; i < 8; i++) tot += red[i];
    float mean = tot * (1.f / Hn);
    __syncthreads();

    float dv = v - mean;
    float r2 = dv * dv;
#pragma unroll
    for (int off = 16; off; off >>= 1) r2 += __shfl_xor_sync(0xffffffffu, r2, off);
    if ((n & 31) == 0) red[n >> 5] = r2;
    __syncthreads();
    tot = 0.f;
#pragma unroll
    for (int i = 0; i < 8; i++) tot += red[i];
    float var = tot * (1.f / Hn);

    float o = lnw[n] * dv * rsqrtf(var + LNEPS) + lnb[n];
    g_center[b * Hn + n] = o;
    dst[b * Hn + n] = o;
}

// ---------------------------------------------------------------------------
extern "C" void kernel_launch(void* const* d_in, const int* in_sizes, int n_in,
                              void* d_out, int out_size) {
    const float* x     = (const float*)d_in[0];
    const float* satWq = (const float*)d_in[1];  const float* satbq = (const float*)d_in[2];
    const float* satWk = (const float*)d_in[3];  const float* satbk = (const float*)d_in[4];
    const float* satWv = (const float*)d_in[5];  const float* satbv = (const float*)d_in[6];
    const float* satWo = (const float*)d_in[7];  const float* satbo = (const float*)d_in[8];
    const float* relWq = (const float*)d_in[9];  const float* relbq = (const float*)d_in[10];
    const float* relWk = (const float*)d_in[11]; const float* relbk = (const float*)d_in[12];
    const float* relWv = (const float*)d_in[13]; const float* relbv = (const float*)d_in[14];
    const float* relWo = (const float*)d_in[15]; const float* relbo = (const float*)d_in[16];
    const float* slnw  = (const float*)d_in[17]; const float* slnb  = (const float*)d_in[18];
    const float* rlnw  = (const float*)d_in[19]; const float* rlnb  = (const float*)d_in[20];
    float* out = (float*)d_out;

    float *cur, *Q, *Kc, *Vc, *Kx, *Vx, *tmp, *Krel, *Vrel, *center;
    __half *curP, *ctxP, *BT;
    cudaGetSymbolAddress((void**)&cur,  g_cur);
    cudaGetSymbolAddress((void**)&Q,    g_Q);
    cudaGetSymbolAddress((void**)&Kc,   g_Kc);
    cudaGetSymbolAddress((void**)&Vc,   g_Vc);
    cudaGetSymbolAddress((void**)&Kx,   g_Kx);
    cudaGetSymbolAddress((void**)&Vx,   g_Vx);
    cudaGetSymbolAddress((void**)&tmp,  g_tmp);
    cudaGetSymbolAddress((void**)&Krel, g_Krel);
    cudaGetSymbolAddress((void**)&Vrel, g_Vrel);
    cudaGetSymbolAddress((void**)&curP, g_curP);
    cudaGetSymbolAddress((void**)&ctxP, g_ctxP);
    cudaGetSymbolAddress((void**)&BT,   g_BT);
    cudaGetSymbolAddress((void**)&center, g_center);

    cudaFuncSetAttribute(hgemm2, cudaFuncAttributeMaxDynamicSharedMemorySize,
                         GEMM_SMEM);

    // weight prep: 0 satWq, 1 satWk, 2 satWv, 3 satWo, 4 relWk, 5 relWv
    wprep_kernel<<<dim3(Hn, 6), Hn>>>(satWq, satWk, satWv, satWo, relWk, relWv);

    splitcopy_kernel<<<Mn * Hn / 8 / 256, 256>>>(x);
    meanpart_kernel<<<dim3(16, Bn), Hn>>>(x);

    const __half* Wq = BT + (size_t)0 * Hn * Hn;
    const __half* Wk = BT + (size_t)1 * Hn * Hn;
    const __half* Wv = BT + (size_t)2 * Hn * Hn;
    const __half* Wo = BT + (size_t)3 * Hn * Hn;
    const __half* Wrk = BT + (size_t)4 * Hn * Hn;
    const __half* Wrv = BT + (size_t)5 * Hn * Hn;

    for (int it = 0; it < 2; it++) {
        proj_center_kernel<<<5 * Bn, Hn>>>(satWk, satbk, satWv, satbv,
                                           relWq, relbq, relWk, relbk, relWv, relbv,
                                           it == 0 ? 1 : 0);
        // iter 0: cur == x, so K/V projections double as loop-invariant Kx/Vx
        float* Kdst = (it == 0) ? Kx : Kc;
        float* Vdst = (it == 0) ? Vx : Vc;
        hgemm2<<<dim3(Mn / 128, 3), 256, GEMM_SMEM>>>(
            curP, Wq, Wk, Wv, satbq, satbk, satbv, Q, Kdst, Vdst);
        sat_attn_kernel<<<Mn, 256>>>(Kdst, Vdst);
        hgemm2<<<dim3(Mn / 128, 1), 256, GEMM_SMEM>>>(
            ctxP, Wo, Wo, Wo, satbo, satbo, satbo, tmp, tmp, tmp);
        // iter 1 writes final token output directly
        float* lnout = (it == 0) ? cur : out;
        ln_rows_kernel<<<Mn / 8, 256>>>(tmp, cur, lnout, slnw, slnb);
        hgemm2<<<dim3(Mn / 128, 2), 256, GEMM_SMEM>>>(
            curP, Wrk, Wrv, Wrv, relbk, relbv, relbv, Krel, Vrel, Vrel);
        rel_part_kernel<<<Bn * NHn * 8, 256>>>();
        float* cdst = (it == 0) ? center : (out + (size_t)Mn * Hn);
        rel_epi_kernel<<<Bn, Hn>>>(relWo, relbo, rlnw, rlnb, cdst);
    }
}

// round 8
// speedup vs baseline: 3.2745x; 1.2848x over previous
#include <cuda_runtime.h>
#include <cuda_fp16.h>
#include <math.h>
#include <stdint.h>

// ---------------------------------------------------------------------------
// StarTransformerLayer, GB300 (compute_103 -> mma.sync path).
// B=8, L=4096, H=256, NH=8, HD=32, 2 iterations.
// GEMMs: pure fp16 inputs (A=fp16(a), B=fp16(w)), fp32 accumulate, K=256.
// Calibrated error model: W-rounding 4.8e-4 (measured R7) + A-rounding ~same,
// independent -> ~6.8e-4 combined, under the 1e-3 gate.
// ---------------------------------------------------------------------------

namespace {
constexpr int Bn  = 8;
constexpr int Ln  = 4096;
constexpr int Hn  = 256;
constexpr int NHn = 8;
constexpr int HDn = 32;
constexpr int Mn  = Bn * Ln;          // 32768
constexpr int KA  = 256;              // fp16 A columns
constexpr float SCALE = 0.17677669529663688f;   // 1/sqrt(32)
constexpr float LNEPS = 1e-12f;
// GEMM tiling
constexpr int KC   = 32;
constexpr int NC   = KA / KC;         // 8 chunks
constexpr int LDA  = 40;              // 32 + 8 pad (halfs)
constexpr int LDB  = 264;             // 256 + 8 pad (halfs)
constexpr int ASZ  = 128 * LDA;       // 5120 halfs
constexpr int BSZ  = KC * LDB;        // 8448 halfs
constexpr int STG  = ASZ + BSZ;       // 13568 halfs
constexpr int GEMM_SMEM = STG * 2 * 4;   // 108544 bytes (4 stages)
}

// ---- scratch (device globals) ---------------------------------------------
__device__ float  g_cur [Mn * Hn];
__device__ __align__(16) __half g_curP[(size_t)Mn * KA];
__device__ __align__(16) __half g_ctxP[(size_t)Mn * KA];
__device__ __align__(16) __half g_BT  [6 * (size_t)Hn * Hn];
__device__ float  g_Q   [Mn * Hn];
__device__ float  g_Kc  [Mn * Hn];
__device__ float  g_Vc  [Mn * Hn];
__device__ float  g_Kx  [Mn * Hn];
__device__ float  g_Vx  [Mn * Hn];
__device__ float  g_tmp [Mn * Hn];
__device__ float  g_Krel[Mn * Hn];
__device__ float  g_Vrel[Mn * Hn];

__device__ float g_center[Bn * Hn];
// center projections as 4 k-partials: [ks][sel][b*Hn+n]
// sel: 0=Kcen 1=Vcen 2=Qrel 3=Krel0 4=Vrel0
__device__ float g_cproj[4][5][Bn * Hn];
__device__ float g_cpart[Bn * 16 * Hn];

__device__ float g_pm[512];
__device__ float g_ps[512];
__device__ float g_pacc[512 * HDn];

// ---------------------------------------------------------------------------
// helpers
// ---------------------------------------------------------------------------
__device__ __forceinline__ uint32_t smem_u32(const void* p) {
    uint32_t a;
    asm("{ .reg .u64 t; cvta.to.shared.u64 t, %1; cvt.u32.u64 %0, t; }"
        : "=r"(a) : "l"(p));
    return a;
}
__device__ __forceinline__ void cp16(uint32_t s, const void* g) {
    asm volatile("cp.async.cg.shared.global [%0], [%1], 16;" :: "r"(s), "l"(g));
}
__device__ __forceinline__ void cp_commit() {
    asm volatile("cp.async.commit_group;" ::: "memory");
}
__device__ __forceinline__ void ldm_x4(uint32_t* r, uint32_t a) {
    asm volatile("ldmatrix.sync.aligned.m8n8.x4.shared.b16 {%0,%1,%2,%3}, [%4];"
                 : "=r"(r[0]), "=r"(r[1]), "=r"(r[2]), "=r"(r[3]) : "r"(a));
}
__device__ __forceinline__ void ldm_x4t(uint32_t* r, uint32_t a) {
    asm volatile("ldmatrix.sync.aligned.m8n8.x4.trans.shared.b16 {%0,%1,%2,%3}, [%4];"
                 : "=r"(r[0]), "=r"(r[1]), "=r"(r[2]), "=r"(r[3]) : "r"(a));
}
__device__ __forceinline__ void mma16816(float* c, const uint32_t* a,
                                         const uint32_t* b) {
    asm volatile(
        "mma.sync.aligned.m16n8k16.row.col.f32.f16.f16.f32 "
        "{%0,%1,%2,%3}, {%4,%5,%6,%7}, {%8,%9}, {%0,%1,%2,%3};"
        : "+f"(c[0]), "+f"(c[1]), "+f"(c[2]), "+f"(c[3])
        : "r"(a[0]), "r"(a[1]), "r"(a[2]), "r"(a[3]), "r"(b[0]), "r"(b[1]));
}

// ---------------------------------------------------------------------------
// GEMM: C[M,256] = A[M,256](fp16) @ B[256,256](fp16) + bias.  CTA 128x256,
// 8 warps 64x64, KC=32, 4-stage cp.async. blockIdx.y selects weight set.
// ---------------------------------------------------------------------------
__global__ __launch_bounds__(256, 1)
void hgemm2(const __half* __restrict__ Ap,
            const __half* B0, const __half* B1, const __half* B2,
            const float* bias0, const float* bias1, const float* bias2,
            float* C0, float* C1, float* C2) {
    extern __shared__ __align__(16) __half smh[];
    const int tid = threadIdx.x;
    const int bm = blockIdx.x * 128;
    const int wsel = blockIdx.y;
    const __half* Bp  = (wsel == 0) ? B0 : (wsel == 1) ? B1 : B2;
    const float*  bias = (wsel == 0) ? bias0 : (wsel == 1) ? bias1 : bias2;
    float*        C   = (wsel == 0) ? C0 : (wsel == 1) ? C1 : C2;
    const uint32_t sbase = smem_u32(smh);

    auto load_chunk = [&](int j, int s) {
        const uint32_t st = sbase + (uint32_t)(s * STG) * 2;
#pragma unroll
        for (int i = 0; i < 2; i++) {          // A: 512 16B segs
            int seg = tid + i * 256;
            int r = seg >> 2, c = seg & 3;
            cp16(st + (uint32_t)(r * LDA + c * 8) * 2,
                 Ap + (size_t)(bm + r) * KA + j * KC + c * 8);
        }
#pragma unroll
        for (int i = 0; i < 4; i++) {          // B: 1024 16B segs
            int seg = tid + i * 256;
            int r = seg >> 5, c = seg & 31;
            cp16(st + (uint32_t)(ASZ + r * LDB + c * 8) * 2,
                 Bp + (size_t)(j * KC + r) * Hn + c * 8);
        }
        cp_commit();
    };

    const int warp = tid >> 5, lane = tid & 31;
    const int wm = (warp & 1) * 64;
    const int wn = (warp >> 1) * 64;
    const int lr = lane & 15;
    const int lg8 = (lane >> 4) * 8;

    float acc[4][8][4];
#pragma unroll
    for (int mi = 0; mi < 4; mi++)
#pragma unroll
        for (int ni = 0; ni < 8; ni++)
#pragma unroll
            for (int k = 0; k < 4; k++) acc[mi][ni][k] = 0.f;

    load_chunk(0, 0);
    load_chunk(1, 1);
    load_chunk(2, 2);

    for (int j = 0; j < NC; j++) {
        asm volatile("cp.async.wait_group 2;" ::: "memory");
        __syncthreads();
        if (j + 3 < NC) load_chunk(j + 3, (j + 3) & 3);
        else            cp_commit();           // constant group depth

        const uint32_t st = sbase + (uint32_t)((j & 3) * STG) * 2;
#pragma unroll
        for (int ks = 0; ks < KC; ks += 16) {
            uint32_t a[4][4];
#pragma unroll
            for (int mi = 0; mi < 4; mi++)
                ldm_x4(a[mi], st + (uint32_t)((wm + mi * 16 + lr) * LDA + ks + lg8) * 2);
            uint32_t b[4][4];
#pragma unroll
            for (int np = 0; np < 4; np++)
                ldm_x4t(b[np], st + (uint32_t)(ASZ + (ks + lr) * LDB
                                               + wn + np * 16 + lg8) * 2);
#pragma unroll
            for (int mi = 0; mi < 4; mi++)
#pragma unroll
                for (int ni = 0; ni < 8; ni++)
                    mma16816(acc[mi][ni], a[mi], &b[ni >> 1][(ni & 1) * 2]);
        }
    }

    const int g = lane >> 2, tg = (lane & 3) * 2;
#pragma unroll
    for (int mi = 0; mi < 4; mi++) {
#pragma unroll
        for (int ni = 0; ni < 8; ni++) {
            int row = bm + wm + mi * 16 + g;
            int col = wn + ni * 8 + tg;
            float b0 = bias[col], b1 = bias[col + 1];
            float2 o0 = { acc[mi][ni][0] + b0, acc[mi][ni][1] + b1 };
            float2 o1 = { acc[mi][ni][2] + b0, acc[mi][ni][3] + b1 };
            *(float2*)(C + (size_t)row * Hn + col) = o0;
            *(float2*)(C + (size_t)(row + 8) * Hn + col) = o1;
        }
    }
}

// ---------------------------------------------------------------------------
// weight prep: fp16(W)[256x256] per weight, all 6 in one launch
// ---------------------------------------------------------------------------
__global__ void wprep_kernel(const float* W0, const float* W1, const float* W2,
                             const float* W3, const float* W4, const float* W5) {
    const float* Ws[6] = {W0, W1, W2, W3, W4, W5};
    int wi = blockIdx.y;
    int k = blockIdx.x, n = threadIdx.x;
    g_BT[(size_t)wi * Hn * Hn + (size_t)k * Hn + n] =
        __float2half_rn(Ws[wi][(size_t)k * Hn + n]);
}

// ---------------------------------------------------------------------------
// x -> cur (fp32) + curP (fp16)
// ---------------------------------------------------------------------------
__global__ void splitcopy_kernel(const float* __restrict__ x) {
    int t = blockIdx.x * blockDim.x + threadIdx.x;   // Mn*Hn/8
    int row = t >> 5;
    int k0 = (t & 31) * 8;
    const float4* src = (const float4*)(x + (size_t)row * Hn + k0);
    float4* dst = (float4*)(g_cur + (size_t)row * Hn + k0);
    float4 v0 = src[0], v1 = src[1];
    dst[0] = v0; dst[1] = v1;
    __half hi[8];
    float vv[8] = {v0.x, v0.y, v0.z, v0.w, v1.x, v1.y, v1.z, v1.w};
#pragma unroll
    for (int j = 0; j < 8; j++) hi[j] = __float2half_rn(vv[j]);
    *(uint4*)(g_curP + (size_t)row * KA + k0) = *(uint4*)hi;
}

// partial column sums of x over L (stage 1 of mean)
__global__ void meanpart_kernel(const float* __restrict__ x) {
    int c = blockIdx.x, b = blockIdx.y, h = threadIdx.x;
    const float* p = x + ((size_t)b * Ln + c * 256) * Hn + h;
    float s = 0.f;
    for (int l = 0; l < 256; l++) s += p[(size_t)l * Hn];
    g_cpart[(b * 16 + c) * Hn + h] = s;
}

// ---------------------------------------------------------------------------
// center projections, 4-way k-split: grid (5*Bn, 4). Block (b,sel,ks) computes
// partial dot over k in [ks*64, ks*64+64) -> g_cproj[ks][sel][b*Hn+n].
// iter 0 (use_cpart): center finished from cpart; sel==0 stores g_center.
// ---------------------------------------------------------------------------
__global__ void proj_center_kernel(
    const float* __restrict__ satWk, const float* __restrict__ satbk,
    const float* __restrict__ satWv, const float* __restrict__ satbv,
    const float* __restrict__ relWq, const float* __restrict__ relbq,
    const float* __restrict__ relWk, const float* __restrict__ relbk,
    const float* __restrict__ relWv, const float* __restrict__ relbv,
    int use_cpart) {
    __shared__ float c[64];
    int b   = blockIdx.x % Bn;
    int sel = blockIdx.x / Bn;
    int ks  = blockIdx.y;
    int n   = threadIdx.x;
    int k0  = ks * 64;
    if (n < 64) {
        int k = k0 + n;
        float v;
        if (use_cpart) {
            float s = 0.f;
#pragma unroll
            for (int i = 0; i < 16; i++) s += g_cpart[(b * 16 + i) * Hn + k];
            v = s * (1.f / Ln);
            if (sel == 0) g_center[b * Hn + k] = v;
        } else {
            v = g_center[b * Hn + k];
        }
        c[n] = v;
    }
    __syncthreads();
    const float* W; const float* bi;
    switch (sel) {
        case 0: W = satWk; bi = satbk; break;
        case 1: W = satWv; bi = satbv; break;
        case 2: W = relWq; bi = relbq; break;
        case 3: W = relWk; bi = relbk; break;
        default: W = relWv; bi = relbv; break;
    }
    float s = 0.f;
#pragma unroll 8
    for (int k = 0; k < 64; k++) s += c[k] * W[(size_t)(k0 + k) * Hn + n];
    if (ks == 0) s += bi[n];
    g_cproj[ks][sel][b * Hn + n] = s;
}

// ---------------------------------------------------------------------------
// satellite attention -> writes ctxP (fp16)
// ---------------------------------------------------------------------------
__global__ __launch_bounds__(256)
void sat_attn_kernel(const float* __restrict__ Kc, const float* __restrict__ Vc) {
    int token = blockIdx.x;
    int b = token >> 12;
    int l = token & (Ln - 1);
    int h = threadIdx.x >> 5;
    int d = threadIdx.x & 31;
    int col = h * HDn + d;

    size_t ic   = (size_t)token * Hn + col;
    int lb = (l + 1) & (Ln - 1);
    int la = (l == 0) ? (Ln - 1) : 0;
    size_t ibe  = ((size_t)(b * Ln + lb)) * Hn + col;
    size_t iaf  = ((size_t)(b * Ln + la)) * Hn + col;
    int icen = b * Hn + col;

    float kcen = g_cproj[0][0][icen] + g_cproj[1][0][icen]
               + g_cproj[2][0][icen] + g_cproj[3][0][icen];
    float vcen = g_cproj[0][1][icen] + g_cproj[1][1][icen]
               + g_cproj[2][1][icen] + g_cproj[3][1][icen];

    float q  = g_Q[ic];
    float s0 = q * Kc[ibe];
    float s1 = q * Kc[ic];
    float s2 = q * Kc[iaf];
    float s3 = q * g_Kx[ic];
    float s4 = q * kcen;
#pragma unroll
    for (int off = 16; off; off >>= 1) {
        s0 += __shfl_xor_sync(0xffffffffu, s0, off);
        s1 += __shfl_xor_sync(0xffffffffu, s1, off);
        s2 += __shfl_xor_sync(0xffffffffu, s2, off);
        s3 += __shfl_xor_sync(0xffffffffu, s3, off);
        s4 += __shfl_xor_sync(0xffffffffu, s4, off);
    }
    s0 *= SCALE; s1 *= SCALE; s2 *= SCALE; s3 *= SCALE; s4 *= SCALE;
    float mx = fmaxf(fmaxf(fmaxf(s0, s1), fmaxf(s2, s3)), s4);
    float e0 = expf(s0 - mx), e1 = expf(s1 - mx), e2 = expf(s2 - mx);
    float e3 = expf(s3 - mx), e4 = expf(s4 - mx);
    float inv = 1.f / (e0 + e1 + e2 + e3 + e4);
    float ctx = (e0 * Vc[ibe] + e1 * Vc[ic] + e2 * Vc[iaf] +
                 e3 * g_Vx[ic] + e4 * vcen) * inv;

    g_ctxP[(size_t)token * KA + col] = __float2half_rn(ctx);
}

// ---------------------------------------------------------------------------
// LN(relu(tmp + curIn)) -> outF (fp32) + curP (fp16), warp per row
// ---------------------------------------------------------------------------
__global__ __launch_bounds__(256)
void ln_rows_kernel(const float* __restrict__ tmp, const float* __restrict__ curIn,
                    float* __restrict__ outF,
                    const float* __restrict__ w, const float* __restrict__ bvec) {
    int warp = threadIdx.x >> 5;
    int lane = threadIdx.x & 31;
    int row = blockIdx.x * 8 + warp;
    int k0 = lane * 8;
    size_t base = (size_t)row * Hn + k0;

    float4 t0 = *(const float4*)(tmp + base);
    float4 t1 = *(const float4*)(tmp + base + 4);
    float4 c0 = *(const float4*)(curIn + base);
    float4 c1 = *(const float4*)(curIn + base + 4);
    float v[8] = { fmaxf(t0.x + c0.x, 0.f), fmaxf(t0.y + c0.y, 0.f),
                   fmaxf(t0.z + c0.z, 0.f), fmaxf(t0.w + c0.w, 0.f),
                   fmaxf(t1.x + c1.x, 0.f), fmaxf(t1.y + c1.y, 0.f),
                   fmaxf(t1.z + c1.z, 0.f), fmaxf(t1.w + c1.w, 0.f) };

    float s = 0.f;
#pragma unroll
    for (int j = 0; j < 8; j++) s += v[j];
#pragma unroll
    for (int off = 16; off; off >>= 1) s += __shfl_xor_sync(0xffffffffu, s, off);
    float mean = s * (1.f / Hn);

    float s2 = 0.f;
#pragma unroll
    for (int j = 0; j < 8; j++) { float d = v[j] - mean; s2 += d * d; }
#pragma unroll
    for (int off = 16; off; off >>= 1) s2 += __shfl_xor_sync(0xffffffffu, s2, off);
    float rstd = rsqrtf(s2 * (1.f / Hn) + LNEPS);

    float4 w0 = *(const float4*)(w + k0);
    float4 w1 = *(const float4*)(w + k0 + 4);
    float4 b0 = *(const float4*)(bvec + k0);
    float4 b1 = *(const float4*)(bvec + k0 + 4);
    float ww[8] = {w0.x, w0.y, w0.z, w0.w, w1.x, w1.y, w1.z, w1.w};
    float bb[8] = {b0.x, b0.y, b0.z, b0.w, b1.x, b1.y, b1.z, b1.w};

    float o[8];
    __half hi[8];
#pragma unroll
    for (int j = 0; j < 8; j++) {
        o[j] = ww[j] * (v[j] - mean) * rstd + bb[j];
        hi[j] = __float2half_rn(o[j]);
    }
    *(float4*)(outF + base)     = make_float4(o[0], o[1], o[2], o[3]);
    *(float4*)(outF + base + 4) = make_float4(o[4], o[5], o[6], o[7]);
    *(uint4*)(g_curP + (size_t)row * KA + k0) = *(uint4*)hi;
}

// ---------------------------------------------------------------------------
// relay attention split-KV (512 blocks)
// ---------------------------------------------------------------------------
__global__ __launch_bounds__(256)
void rel_part_kernel() {
    __shared__ float qs[HDn];
    __shared__ float sm[256], ss[256];
    __shared__ float sacc[256 * HDn];

    int bh = blockIdx.x >> 3;
    int sp = blockIdx.x & 7;
    int b = bh >> 3, h = bh & 7;
    int t = threadIdx.x;

    if (t < HDn) {
        int i = b * Hn + h * HDn + t;
        qs[t] = g_cproj[0][2][i] + g_cproj[1][2][i]
              + g_cproj[2][2][i] + g_cproj[3][2][i];
    }
    __syncthreads();

    float m = -1e30f, ssum = 0.f;
    float acc[HDn];
#pragma unroll
    for (int d = 0; d < HDn; d++) acc[d] = 0.f;

    for (int j = sp * 256 + t; j <= Ln; j += 2048) {
        float s = 0.f;
        float vv0[HDn];
        if (j == 0) {
            int ib = b * Hn + h * HDn;
#pragma unroll
            for (int d = 0; d < HDn; d++) {
                float kv = g_cproj[0][3][ib + d] + g_cproj[1][3][ib + d]
                         + g_cproj[2][3][ib + d] + g_cproj[3][3][ib + d];
                s += qs[d] * kv;
                vv0[d] = g_cproj[0][4][ib + d] + g_cproj[1][4][ib + d]
                       + g_cproj[2][4][ib + d] + g_cproj[3][4][ib + d];
            }
        } else {
            size_t base = ((size_t)(b * Ln + j - 1)) * Hn + h * HDn;
            const float* kv = g_Krel + base;
            const float* vv = g_Vrel + base;
#pragma unroll
            for (int d = 0; d < HDn; d += 4) {
                float4 k4 = *(const float4*)(kv + d);
                float4 v4 = *(const float4*)(vv + d);
                s += qs[d] * k4.x + qs[d + 1] * k4.y + qs[d + 2] * k4.z + qs[d + 3] * k4.w;
                vv0[d + 0] = v4.x; vv0[d + 1] = v4.y;
                vv0[d + 2] = v4.z; vv0[d + 3] = v4.w;
            }
        }
        s *= SCALE;
        float mn = fmaxf(m, s);
        float corr = expf(m - mn);
        float p = expf(s - mn);
        ssum = ssum * corr + p;
#pragma unroll
        for (int d = 0; d < HDn; d++)
            acc[d] = acc[d] * corr + p * vv0[d];
        m = mn;
    }

    sm[t] = m; ss[t] = ssum;
#pragma unroll
    for (int d = 0; d < HDn; d++) sacc[t * HDn + d] = acc[d];
    __syncthreads();

    for (int stride = 128; stride > 0; stride >>= 1) {
        if (t < stride) {
            float m1 = sm[t], m2 = sm[t + stride];
            float mn = fmaxf(m1, m2);
            float c1 = expf(m1 - mn), c2 = expf(m2 - mn);
            sm[t] = mn;
            ss[t] = ss[t] * c1 + ss[t + stride] * c2;
            for (int d = 0; d < HDn; d++)
                sacc[t * HDn + d] = sacc[t * HDn + d] * c1 + sacc[(t + stride) * HDn + d] * c2;
        }
        __syncthreads();
    }

    if (t == 0) { g_pm[blockIdx.x] = sm[0]; g_ps[blockIdx.x] = ss[0]; }
    if (t < HDn) g_pacc[blockIdx.x * HDn + t] = sacc[t];
}

// ---------------------------------------------------------------------------
// relay epilogue (split-KV combine folded in):
// dst = LN(relu(relctx @ Wo + bo + center)); also updates g_center
// ---------------------------------------------------------------------------
__global__ __launch_bounds__(256)
void rel_epi_kernel(const float* __restrict__ Wo, const float* __restrict__ bo,
                    const float* __restrict__ lnw, const float* __restrict__ lnb,
                    float* __restrict__ dst) {
    __shared__ float cx[Hn];
    __shared__ float red[8];
    int b = blockIdx.x;
    int n = threadIdx.x;
    {
        int h = n >> 5, d = n & 31;
        int bh = b * 8 + h;
        float m = -1e30f;
#pragma unroll
        for (int sp = 0; sp < 8; sp++) m = fmaxf(m, g_pm[bh * 8 + sp]);
        float s = 0.f, a = 0.f;
#pragma unroll
        for (int sp = 0; sp < 8; sp++) {
            float c = expf(g_pm[bh * 8 + sp] - m);
            s += g_ps[bh * 8 + sp] * c;
            a += g_pacc[(bh * 8 + sp) * HDn + d] * c;
        }
        cx[n] = a / s;
    }
    float resid = g_center[b * Hn + n];
    __syncthreads();
    float s = 0.f;
#pragma unroll 8
    for (int k = 0; k < Hn; k++) s += cx[k] * Wo[k * Hn + n];
    float v = fmaxf(s + bo[n] + resid, 0.f);

    float r = v;
#pragma unroll
    for (int off = 16; off; off >>= 1) r += __shfl_xor_sync(0xffffffffu, r, off);
    if ((n & 31) == 0) red[n >> 5] = r;
    __syncthreads();
    float tot = 0.f;
#pragma unroll
    for (int i = 0; i < 8; i++) tot += red[i];
    float mean = tot * (1.f / Hn);
    __syncthreads();

    float dv = v - mean;
    float r2 = dv * dv;
#pragma unroll
    for (int off = 16; off; off >>= 1) r2 += __shfl_xor_sync(0xffffffffu, r2, off);
    if ((n & 31) == 0) red[n >> 5] = r2;
    __syncthreads();
    tot = 0.f;
#pragma unroll
    for (int i = 0; i < 8; i++) tot += red[i];
    float var = tot * (1.f / Hn);

    float o = lnw[n] * dv * rsqrtf(var + LNEPS) + lnb[n];
    g_center[b * Hn + n] = o;
    dst[b * Hn + n] = o;
}

// ---------------------------------------------------------------------------
extern "C" void kernel_launch(void* const* d_in, const int* in_sizes, int n_in,
                              void* d_out, int out_size) {
    const float* x     = (const float*)d_in[0];
    const float* satWq = (const float*)d_in[1];  const float* satbq = (const float*)d_in[2];
    const float* satWk = (const float*)d_in[3];  const float* satbk = (const float*)d_in[4];
    const float* satWv = (const float*)d_in[5];  const float* satbv = (const float*)d_in[6];
    const float* satWo = (const float*)d_in[7];  const float* satbo = (const float*)d_in[8];
    const float* relWq = (const float*)d_in[9];  const float* relbq = (const float*)d_in[10];
    const float* relWk = (const float*)d_in[11]; const float* relbk = (const float*)d_in[12];
    const float* relWv = (const float*)d_in[13]; const float* relbv = (const float*)d_in[14];
    const float* relWo = (const float*)d_in[15]; const float* relbo = (const float*)d_in[16];
    const float* slnw  = (const float*)d_in[17]; const float* slnb  = (const float*)d_in[18];
    const float* rlnw  = (const float*)d_in[19]; const float* rlnb  = (const float*)d_in[20];
    float* out = (float*)d_out;

    float *cur, *Q, *Kc, *Vc, *Kx, *Vx, *tmp, *Krel, *Vrel, *center;
    __half *curP, *ctxP, *BT;
    cudaGetSymbolAddress((void**)&cur,  g_cur);
    cudaGetSymbolAddress((void**)&Q,    g_Q);
    cudaGetSymbolAddress((void**)&Kc,   g_Kc);
    cudaGetSymbolAddress((void**)&Vc,   g_Vc);
    cudaGetSymbolAddress((void**)&Kx,   g_Kx);
    cudaGetSymbolAddress((void**)&Vx,   g_Vx);
    cudaGetSymbolAddress((void**)&tmp,  g_tmp);
    cudaGetSymbolAddress((void**)&Krel, g_Krel);
    cudaGetSymbolAddress((void**)&Vrel, g_Vrel);
    cudaGetSymbolAddress((void**)&curP, g_curP);
    cudaGetSymbolAddress((void**)&ctxP, g_ctxP);
    cudaGetSymbolAddress((void**)&BT,   g_BT);
    cudaGetSymbolAddress((void**)&center, g_center);

    cudaFuncSetAttribute(hgemm2, cudaFuncAttributeMaxDynamicSharedMemorySize,
                         GEMM_SMEM);

    // weight prep: 0 satWq, 1 satWk, 2 satWv, 3 satWo, 4 relWk, 5 relWv
    wprep_kernel<<<dim3(Hn, 6), Hn>>>(satWq, satWk, satWv, satWo, relWk, relWv);

    splitcopy_kernel<<<Mn * Hn / 8 / 256, 256>>>(x);
    meanpart_kernel<<<dim3(16, Bn), Hn>>>(x);

    const __half* Wq = BT + (size_t)0 * Hn * Hn;
    const __half* Wk = BT + (size_t)1 * Hn * Hn;
    const __half* Wv = BT + (size_t)2 * Hn * Hn;
    const __half* Wo = BT + (size_t)3 * Hn * Hn;
    const __half* Wrk = BT + (size_t)4 * Hn * Hn;
    const __half* Wrv = BT + (size_t)5 * Hn * Hn;

    for (int it = 0; it < 2; it++) {
        proj_center_kernel<<<dim3(5 * Bn, 4), Hn>>>(
            satWk, satbk, satWv, satbv, relWq, relbq, relWk, relbk, relWv, relbv,
            it == 0 ? 1 : 0);
        // iter 0: cur == x, so K/V projections double as loop-invariant Kx/Vx
        float* Kdst = (it == 0) ? Kx : Kc;
        float* Vdst = (it == 0) ? Vx : Vc;
        hgemm2<<<dim3(Mn / 128, 3), 256, GEMM_SMEM>>>(
            curP, Wq, Wk, Wv, satbq, satbk, satbv, Q, Kdst, Vdst);
        sat_attn_kernel<<<Mn, 256>>>(Kdst, Vdst);
        hgemm2<<<dim3(Mn / 128, 1), 256, GEMM_SMEM>>>(
            ctxP, Wo, Wo, Wo, satbo, satbo, satbo, tmp, tmp, tmp);
        float* lnout = (it == 0) ? cur : out;
        ln_rows_kernel<<<Mn / 8, 256>>>(tmp, cur, lnout, slnw, slnb);
        hgemm2<<<dim3(Mn / 128, 2), 256, GEMM_SMEM>>>(
            curP, Wrk, Wrv, Wrv, relbk, relbv, relbv, Krel, Vrel, Vrel);
        rel_part_kernel<<<Bn * NHn * 8, 256>>>();
        float* cdst = (it == 0) ? center : (out + (size_t)Mn * Hn);
        rel_epi_kernel<<<Bn, Hn>>>(relWo, relbo, rlnw, rlnb, cdst);
    }
}